// round 6
// baseline (speedup 1.0000x reference)
#include <cuda_runtime.h>
#include <cuda_fp16.h>
#include <math.h>
#include <stdint.h>

// Problem constants
#define BATCH 4
#define SEQ   2048
#define EMB   1024
#define HEADS 16
#define HDIM  64
#define TOK   (BATCH * SEQ)          // 8192
#define QKVF  (3 * EMB)              // 3072

// Scratch (device globals — no allocation allowed)
__device__ __half g_xh[(size_t)TOK * EMB];
__device__ __half g_xl[(size_t)TOK * EMB];
__device__ __half g_wqkvh[(size_t)QKVF * EMB];
__device__ __half g_wouth[(size_t)EMB * EMB];
__device__ __half g_woutl[(size_t)EMB * EMB];
__device__ __half g_qkvh[(size_t)TOK * QKVF];
__device__ __half g_qkvl[(size_t)TOK * QKVF];
__device__ __half g_atth[(size_t)TOK * EMB];
__device__ __half g_attl[(size_t)TOK * EMB];

// ---------------------------------------------------------------------------
// PTX helpers — only sm_80+ features (compute_103 baseline safe)
// ---------------------------------------------------------------------------
__device__ __forceinline__ uint32_t smem_u32(const void* p) {
    uint32_t a;
    asm("{ .reg .u64 t; cvta.to.shared.u64 t, %1; cvt.u32.u64 %0, t; }"
        : "=r"(a) : "l"(p));
    return a;
}

#define CP_ASYNC16(dst, src) \
    asm volatile("cp.async.cg.shared.global [%0], [%1], 16;" :: "r"(dst), "l"(src))
#define CP_COMMIT() asm volatile("cp.async.commit_group;")
#define CP_WAIT(n)  asm volatile("cp.async.wait_group %0;" :: "n"(n))

#define LDMATRIX_X4(r0, r1, r2, r3, addr) \
    asm volatile("ldmatrix.sync.aligned.m8n8.x4.shared.b16 {%0,%1,%2,%3}, [%4];" \
                 : "=r"(r0), "=r"(r1), "=r"(r2), "=r"(r3) : "r"(addr))
#define LDMATRIX_X4_T(r0, r1, r2, r3, addr) \
    asm volatile("ldmatrix.sync.aligned.m8n8.x4.trans.shared.b16 {%0,%1,%2,%3}, [%4];" \
                 : "=r"(r0), "=r"(r1), "=r"(r2), "=r"(r3) : "r"(addr))

#define MMA_F16(c0, c1, c2, c3, a0, a1, a2, a3, b0, b1) \
    asm volatile("mma.sync.aligned.m16n8k16.row.col.f32.f16.f16.f32 " \
                 "{%0,%1,%2,%3}, {%4,%5,%6,%7}, {%8,%9}, {%0,%1,%2,%3};" \
                 : "+f"(c0), "+f"(c1), "+f"(c2), "+f"(c3) \
                 : "r"(a0), "r"(a1), "r"(a2), "r"(a3), "r"(b0), "r"(b1))

__device__ __forceinline__ float ex2f(float x) {
    float y;
    asm("ex2.approx.f32 %0, %1;" : "=f"(y) : "f"(x));
    return y;
}

// pack two floats into fp16x2 hi, residual fp16x2 lo via out-param
__device__ __forceinline__ uint32_t pack_hl(float a, float b, uint32_t& lo) {
    __half2 h = __floats2half2_rn(a, b);
    float ra = a - __low2float(h);
    float rb = b - __high2float(h);
    __half2 r = __floats2half2_rn(ra, rb);
    lo = reinterpret_cast<uint32_t&>(r);
    return reinterpret_cast<uint32_t&>(h);
}

// SW128 XOR swizzle on byte offsets (rows of 128B): conflict-free ldmatrix
#define SW128(off) ((uint32_t)(off) ^ ((((uint32_t)(off)) >> 3) & 0x70))

// ---------------------------------------------------------------------------
// fp32 -> fp16 hi/lo split, and fp32 -> fp16 (hi only)
// ---------------------------------------------------------------------------
__global__ void __launch_bounds__(256) split_kernel(
    const float4* __restrict__ in, __half* __restrict__ hi,
    __half* __restrict__ lo, int n4)
{
    int i = blockIdx.x * blockDim.x + threadIdx.x;
    if (i >= n4) return;
    float4 v = in[i];
    float f[4] = {v.x, v.y, v.z, v.w};
    __half h[4], l[4];
    #pragma unroll
    for (int j = 0; j < 4; j++) {
        h[j] = __float2half_rn(f[j]);
        l[j] = __float2half_rn(f[j] - __half2float(h[j]));
    }
    ((uint2*)hi)[i] = *(uint2*)h;
    ((uint2*)lo)[i] = *(uint2*)l;
}

__global__ void __launch_bounds__(256) tohalf_kernel(
    const float4* __restrict__ in, __half* __restrict__ hi, int n4)
{
    int i = blockIdx.x * blockDim.x + threadIdx.x;
    if (i >= n4) return;
    float4 v = in[i];
    __half h[4] = {__float2half_rn(v.x), __float2half_rn(v.y),
                   __float2half_rn(v.z), __float2half_rn(v.w)};
    ((uint2*)hi)[i] = *(uint2*)h;
}

// ---------------------------------------------------------------------------
// 2-term GEMM:  C = A * B^T,  A = Ah + Al (fp16 planes), B single fp16.
// CTA 128x128, BK=64, 8 warps (2x4, warp 64x32), 2-stage cp.async.
// Output: fp16 hi/lo split (feeds flash).
// ---------------------------------------------------------------------------
#define G2_AH 0
#define G2_AL 16384
#define G2_B  32768
#define G2_STAGE 49152
#define G2_SMEM (2 * G2_STAGE)      // 98304

__global__ void __launch_bounds__(256, 2) gemm_2t_kernel(
    const __half* __restrict__ Ah, const __half* __restrict__ Al,
    const __half* __restrict__ Bh,
    __half* __restrict__ Ch, __half* __restrict__ Cl,
    int M, int N, int K)
{
    extern __shared__ char sm[];
    const uint32_t smb = smem_u32(sm);
    const int tid  = threadIdx.x;
    const int wid  = tid >> 5;
    const int lane = tid & 31;
    const int m0 = blockIdx.y * 128;
    const int n0 = blockIdx.x * 128;
    const int warp_m = (wid >> 3) * 64;   // 2 m-groups
    const int warp_n = (wid & 3) * 32;    // 4 n-groups  (wid>>3 == wid>>2 /2? see below)
    // NOTE: 8 warps as 2x4: m-group = wid>>2, n-group = wid&3
    const int wm = (wid >> 2) * 64;
    const int wn = (wid & 3) * 32;
    (void)warp_m; (void)warp_n;

    const int r = tid >> 3;               // 0..31  (row step 32 over 128 rows)
    const int c = (tid & 7) * 16;         // byte col 0..112

    auto load_chunk = [&](int k0, int stg) {
        const uint32_t sb = smb + stg * G2_STAGE;
        #pragma unroll
        for (int i = 0; i < 4; i++) {
            int rr = r + i * 32;
            uint32_t so = SW128(rr * 128 + c);
            size_t gA = ((size_t)(m0 + rr) * K + k0) * 2 + c;
            size_t gB = ((size_t)(n0 + rr) * K + k0) * 2 + c;
            CP_ASYNC16(sb + G2_AH + so, (const char*)Ah + gA);
            CP_ASYNC16(sb + G2_AL + so, (const char*)Al + gA);
            CP_ASYNC16(sb + G2_B  + so, (const char*)Bh + gB);
        }
    };

    float acc[4][4][4];
    #pragma unroll
    for (int i = 0; i < 4; i++)
        #pragma unroll
        for (int j = 0; j < 4; j++)
            #pragma unroll
            for (int q = 0; q < 4; q++) acc[i][j][q] = 0.f;

    const int nch = K >> 6;               // K/64
    load_chunk(0, 0); CP_COMMIT();

    const int a_row = lane & 15, a_kb = (lane >> 4) * 16;
    const int bq = lane >> 3;
    const int b_r = (bq >> 1) * 8 + (lane & 7), b_kb = (bq & 1) * 16;

    for (int ch = 0; ch < nch; ch++) {
        if (ch + 1 < nch) { load_chunk((ch + 1) << 6, (ch + 1) & 1); CP_COMMIT(); CP_WAIT(1); }
        else              { CP_WAIT(0); }
        __syncthreads();
        const uint32_t sb = smb + (ch & 1) * G2_STAGE;

        #pragma unroll
        for (int ks = 0; ks < 4; ks++) {
            const int kb = ks * 32;
            uint32_t bh[4][2];
            #pragma unroll
            for (int p = 0; p < 2; p++) {
                uint32_t row = (wn + p * 16 + b_r) * 128;
                LDMATRIX_X4(bh[2*p][0], bh[2*p][1], bh[2*p+1][0], bh[2*p+1][1],
                            sb + G2_B + SW128(row + kb + b_kb));
            }
            #pragma unroll
            for (int mi = 0; mi < 4; mi++) {
                uint32_t ah[4], al[4];
                uint32_t row = (wm + mi * 16 + a_row) * 128;
                LDMATRIX_X4(ah[0], ah[1], ah[2], ah[3],
                            sb + G2_AH + SW128(row + kb + a_kb));
                LDMATRIX_X4(al[0], al[1], al[2], al[3],
                            sb + G2_AL + SW128(row + kb + a_kb));
                #pragma unroll
                for (int nj = 0; nj < 4; nj++)
                    MMA_F16(acc[mi][nj][0], acc[mi][nj][1], acc[mi][nj][2], acc[mi][nj][3],
                            ah[0], ah[1], ah[2], ah[3], bh[nj][0], bh[nj][1]);
                #pragma unroll
                for (int nj = 0; nj < 4; nj++)
                    MMA_F16(acc[mi][nj][0], acc[mi][nj][1], acc[mi][nj][2], acc[mi][nj][3],
                            al[0], al[1], al[2], al[3], bh[nj][0], bh[nj][1]);
            }
        }
        __syncthreads();
    }

    const int g = lane >> 2, t = lane & 3;
    #pragma unroll
    for (int mi = 0; mi < 4; mi++) {
        const int row = m0 + wm + mi * 16 + g;
        #pragma unroll
        for (int nj = 0; nj < 4; nj++) {
            const int col = n0 + wn + nj * 8 + t * 2;
            uint32_t lo0, lo1;
            uint32_t hi0 = pack_hl(acc[mi][nj][0], acc[mi][nj][1], lo0);
            uint32_t hi1 = pack_hl(acc[mi][nj][2], acc[mi][nj][3], lo1);
            *(uint32_t*)(Ch + (size_t)row * N + col)       = hi0;
            *(uint32_t*)(Cl + (size_t)row * N + col)       = lo0;
            *(uint32_t*)(Ch + (size_t)(row + 8) * N + col) = hi1;
            *(uint32_t*)(Cl + (size_t)(row + 8) * N + col) = lo1;
        }
    }
}

// ---------------------------------------------------------------------------
// 3-term GEMM (output projection):  C = A*B^T + bias, f32 out.
// A,B fp16 hi/lo; rows [64B hi | 64B lo]. CTA 128x128, BK=32, 3 stages.
// ---------------------------------------------------------------------------
#define G3_TILE (128 * 128)
#define G3_STAGE (2 * G3_TILE)
#define G3_SMEM (3 * G3_STAGE)      // 98304

__global__ void __launch_bounds__(256, 2) gemm_3t_kernel(
    const __half* __restrict__ Ah, const __half* __restrict__ Al,
    const __half* __restrict__ Bh, const __half* __restrict__ Bl,
    const float* __restrict__ bias, float* __restrict__ C,
    int M, int N, int K)
{
    extern __shared__ char sm[];
    const uint32_t smb = smem_u32(sm);
    const int tid  = threadIdx.x;
    const int wid  = tid >> 5;
    const int lane = tid & 31;
    const int m0 = blockIdx.y * 128;
    const int n0 = blockIdx.x * 128;
    const int wm = (wid >> 2) * 64;
    const int wn = (wid & 3) * 32;

    auto load_chunk = [&](int k0, int stg) {
        const uint32_t sb = smb + stg * G3_STAGE;
        #pragma unroll
        for (int i = 0; i < 4; i++) {
            int idx = tid + i * 256;
            int r = idx >> 3;
            int c = (idx & 7) * 16;
            uint32_t so = SW128(r * 128 + c);
            size_t gA = ((size_t)(m0 + r) * K + k0) * 2;
            size_t gB = ((size_t)(n0 + r) * K + k0) * 2;
            const char* sA = (c < 64) ? ((const char*)Ah + gA + c) : ((const char*)Al + gA + c - 64);
            const char* sB = (c < 64) ? ((const char*)Bh + gB + c) : ((const char*)Bl + gB + c - 64);
            CP_ASYNC16(sb + so, sA);
            CP_ASYNC16(sb + G3_TILE + so, sB);
        }
    };

    float acc[4][4][4];
    #pragma unroll
    for (int i = 0; i < 4; i++)
        #pragma unroll
        for (int j = 0; j < 4; j++)
            #pragma unroll
            for (int q = 0; q < 4; q++) acc[i][j][q] = 0.f;

    const int nch = K >> 5;
    load_chunk(0, 0); CP_COMMIT();
    load_chunk(32, 1); CP_COMMIT();

    const int a_row = lane & 15, a_kb = (lane >> 4) * 16;
    const int bq = lane >> 3;
    const int b_r = (bq >> 1) * 8 + (lane & 7), b_kb = (bq & 1) * 16;

    int stg = 0;
    for (int ch = 0; ch < nch; ch++) {
        CP_WAIT(1);
        __syncthreads();
        if (ch + 2 < nch) {
            int s2 = stg + 2; if (s2 >= 3) s2 -= 3;
            load_chunk((ch + 2) << 5, s2);
        }
        CP_COMMIT();

        const uint32_t sb = smb + stg * G3_STAGE;
        #pragma unroll
        for (int ks = 0; ks < 2; ks++) {
            const int kb = ks * 32;
            uint32_t bh[4][2], bl[4][2];
            #pragma unroll
            for (int p = 0; p < 2; p++) {
                uint32_t row = (wn + p * 16 + b_r) * 128;
                LDMATRIX_X4(bh[2*p][0], bh[2*p][1], bh[2*p+1][0], bh[2*p+1][1],
                            sb + G3_TILE + SW128(row + kb + b_kb));
                LDMATRIX_X4(bl[2*p][0], bl[2*p][1], bl[2*p+1][0], bl[2*p+1][1],
                            sb + G3_TILE + SW128(row + 64 + kb + b_kb));
            }
            #pragma unroll
            for (int mi = 0; mi < 4; mi++) {
                uint32_t ah[4], al[4];
                uint32_t row = (wm + mi * 16 + a_row) * 128;
                LDMATRIX_X4(ah[0], ah[1], ah[2], ah[3], sb + SW128(row + kb + a_kb));
                LDMATRIX_X4(al[0], al[1], al[2], al[3], sb + SW128(row + 64 + kb + a_kb));
                #pragma unroll
                for (int nj = 0; nj < 4; nj++)
                    MMA_F16(acc[mi][nj][0], acc[mi][nj][1], acc[mi][nj][2], acc[mi][nj][3],
                            ah[0], ah[1], ah[2], ah[3], bh[nj][0], bh[nj][1]);
                #pragma unroll
                for (int nj = 0; nj < 4; nj++)
                    MMA_F16(acc[mi][nj][0], acc[mi][nj][1], acc[mi][nj][2], acc[mi][nj][3],
                            ah[0], ah[1], ah[2], ah[3], bl[nj][0], bl[nj][1]);
                #pragma unroll
                for (int nj = 0; nj < 4; nj++)
                    MMA_F16(acc[mi][nj][0], acc[mi][nj][1], acc[mi][nj][2], acc[mi][nj][3],
                            al[0], al[1], al[2], al[3], bh[nj][0], bh[nj][1]);
            }
        }
        if (++stg == 3) stg = 0;
    }

    const int g = lane >> 2, t = lane & 3;
    #pragma unroll
    for (int mi = 0; mi < 4; mi++) {
        const int row = m0 + wm + mi * 16 + g;
        #pragma unroll
        for (int nj = 0; nj < 4; nj++) {
            const int col = n0 + wn + nj * 8 + t * 2;
            float b0 = bias[col], b1 = bias[col + 1];
            float2 v0 = {acc[mi][nj][0] + b0, acc[mi][nj][1] + b1};
            float2 v1 = {acc[mi][nj][2] + b0, acc[mi][nj][3] + b1};
            *(float2*)(C + (size_t)row * N + col)       = v0;
            *(float2*)(C + (size_t)(row + 8) * N + col) = v1;
        }
    }
}

// ---------------------------------------------------------------------------
// Flash attention, fp16 2-term (split Q & P; K,V single fp16).
// grid (SEQ/128, HEADS, BATCH), 256 threads, 2-stage KV pipeline.
// ---------------------------------------------------------------------------
#define FA_QH 0
#define FA_QL 16384
#define FA_KV 32768                          // stage s: K plane +0 (8K), V +8K
#define FA_STAGE 16384
#define FA_MADD (FA_KV + 2 * FA_STAGE)       // 65536
#define FA_SMEM (FA_MADD + 2 * 64 * 4)       // 66048
#define FA_C1 0.18033688011112042f           // 0.125 * log2(e)

__global__ void __launch_bounds__(256, 2) flash_mma_kernel(
    const __half* __restrict__ qkh, const __half* __restrict__ qkl,
    const int* __restrict__ mask,
    __half* __restrict__ oh, __half* __restrict__ ol)
{
    extern __shared__ char sm[];
    const uint32_t smb = smem_u32(sm);
    const int tid = threadIdx.x, wid = tid >> 5, lane = tid & 31;
    const int qb = blockIdx.x, h = blockIdx.y, b = blockIdx.z;
    const int tok0 = b * SEQ + qb * 128;

    auto load_kv = [&](int ch) {
        const uint32_t stg = smb + FA_KV + (ch & 1) * FA_STAGE;
        const int k0 = ch * 64;
        #pragma unroll
        for (int i = 0; i < 4; i++) {
            int idx = tid + i * 256;                 // 0..1023
            int tile = idx >> 9;                     // 0=K, 1=V
            int r = (idx >> 3) & 63;
            int c = (idx & 7) * 16;
            size_t gb = ((size_t)(b * SEQ + k0 + r) * QKVF + (tile + 1) * EMB + h * HDIM) * 2 + c;
            CP_ASYNC16(stg + tile * 8192 + SW128(r * 128 + c), (const char*)qkh + gb);
        }
        if (tid < 64) {
            float* md = (float*)(sm + FA_MADD) + (ch & 1) * 64;
            md[tid] = mask[b * SEQ + k0 + tid] ? 0.f : -1e9f;
        }
    };

    // prologue: Q hi/lo planes + KV chunk 0 in one commit group
    #pragma unroll
    for (int i = 0; i < 8; i++) {
        int idx = tid + i * 256;                     // 0..2047
        int t2 = idx >> 10;                          // 0=hi, 1=lo
        int r  = (idx >> 3) & 127;
        int c  = (idx & 7) * 16;
        size_t gb = ((size_t)(tok0 + r) * QKVF + h * HDIM) * 2 + c;
        const char* src = (const char*)(t2 ? qkl : qkh) + gb;
        CP_ASYNC16(smb + (t2 ? FA_QL : FA_QH) + SW128(r * 128 + c), src);
    }
    load_kv(0);
    CP_COMMIT();

    const int g  = lane >> 2, tq = lane & 3;
    const int a_row = lane & 15, a_kb = (lane >> 4) * 16;
    const int bq = lane >> 3;
    const int b_r = (bq >> 1) * 8 + (lane & 7), b_kb = (bq & 1) * 16;
    const int v_r = (bq & 1) * 8 + (lane & 7),  v_nb = (bq >> 1) * 16;

    float m0r = -1e30f, m1r = -1e30f, l0 = 0.f, l1 = 0.f;
    float o[8][4];
    #pragma unroll
    for (int j = 0; j < 8; j++)
        #pragma unroll
        for (int q = 0; q < 4; q++) o[j][q] = 0.f;

    const int NCH = SEQ / 64;
    for (int ch = 0; ch < NCH; ch++) {
        if (ch + 1 < NCH) { load_kv(ch + 1); CP_COMMIT(); CP_WAIT(1); }
        else              { CP_WAIT(0); }
        __syncthreads();
        const uint32_t stg = smb + FA_KV + (ch & 1) * FA_STAGE;

        // ---- S = Q K^T, 2-term (split Q, single K) ----
        float s[8][4];
        #pragma unroll
        for (int j = 0; j < 8; j++)
            #pragma unroll
            for (int q = 0; q < 4; q++) s[j][q] = 0.f;

        #pragma unroll
        for (int ks = 0; ks < 4; ks++) {
            const int kb = ks * 32;
            uint32_t qh[4], ql[4];
            uint32_t qrow = (wid * 16 + a_row) * 128;
            LDMATRIX_X4(qh[0], qh[1], qh[2], qh[3], smb + FA_QH + SW128(qrow + kb + a_kb));
            LDMATRIX_X4(ql[0], ql[1], ql[2], ql[3], smb + FA_QL + SW128(qrow + kb + a_kb));
            uint32_t kh[8][2];
            #pragma unroll
            for (int p = 0; p < 4; p++) {
                uint32_t krow = (p * 16 + b_r) * 128;
                LDMATRIX_X4(kh[2*p][0], kh[2*p][1], kh[2*p+1][0], kh[2*p+1][1],
                            stg + SW128(krow + kb + b_kb));
            }
            #pragma unroll
            for (int j = 0; j < 8; j++)
                MMA_F16(s[j][0], s[j][1], s[j][2], s[j][3],
                        qh[0], qh[1], qh[2], qh[3], kh[j][0], kh[j][1]);
            #pragma unroll
            for (int j = 0; j < 8; j++)
                MMA_F16(s[j][0], s[j][1], s[j][2], s[j][3],
                        ql[0], ql[1], ql[2], ql[3], kh[j][0], kh[j][1]);
        }

        // ---- online softmax (exp2 domain) ----
        const float* md = (const float*)(sm + FA_MADD) + (ch & 1) * 64;
        #pragma unroll
        for (int j = 0; j < 8; j++) {
            float m0 = md[j * 8 + tq * 2];
            float m1 = md[j * 8 + tq * 2 + 1];
            s[j][0] = fmaf(s[j][0], FA_C1, m0);
            s[j][1] = fmaf(s[j][1], FA_C1, m1);
            s[j][2] = fmaf(s[j][2], FA_C1, m0);
            s[j][3] = fmaf(s[j][3], FA_C1, m1);
        }
        float rm0 = -1e30f, rm1 = -1e30f;
        #pragma unroll
        for (int j = 0; j < 8; j++) {
            rm0 = fmaxf(rm0, fmaxf(s[j][0], s[j][1]));
            rm1 = fmaxf(rm1, fmaxf(s[j][2], s[j][3]));
        }
        rm0 = fmaxf(rm0, __shfl_xor_sync(0xffffffffu, rm0, 1));
        rm0 = fmaxf(rm0, __shfl_xor_sync(0xffffffffu, rm0, 2));
        rm1 = fmaxf(rm1, __shfl_xor_sync(0xffffffffu, rm1, 1));
        rm1 = fmaxf(rm1, __shfl_xor_sync(0xffffffffu, rm1, 2));
        const float mn0 = fmaxf(m0r, rm0);
        const float mn1 = fmaxf(m1r, rm1);
        const float al0 = ex2f(m0r - mn0);
        const float al1 = ex2f(m1r - mn1);
        m0r = mn0; m1r = mn1;

        float rs0 = 0.f, rs1 = 0.f;
        #pragma unroll
        for (int j = 0; j < 8; j++) {
            s[j][0] = ex2f(s[j][0] - mn0);
            s[j][1] = ex2f(s[j][1] - mn0);
            s[j][2] = ex2f(s[j][2] - mn1);
            s[j][3] = ex2f(s[j][3] - mn1);
            rs0 += s[j][0] + s[j][1];
            rs1 += s[j][2] + s[j][3];
        }
        rs0 += __shfl_xor_sync(0xffffffffu, rs0, 1);
        rs0 += __shfl_xor_sync(0xffffffffu, rs0, 2);
        rs1 += __shfl_xor_sync(0xffffffffu, rs1, 1);
        rs1 += __shfl_xor_sync(0xffffffffu, rs1, 2);
        l0 = l0 * al0 + rs0;
        l1 = l1 * al1 + rs1;

        #pragma unroll
        for (int j = 0; j < 8; j++) {
            o[j][0] *= al0; o[j][1] *= al0;
            o[j][2] *= al1; o[j][3] *= al1;
        }

        // ---- pack P into A-fragments (hi + residual lo) ----
        uint32_t pah[4][4], pal[4][4];
        #pragma unroll
        for (int ks = 0; ks < 4; ks++) {
            const int j0 = 2 * ks, j1 = 2 * ks + 1;
            pah[ks][0] = pack_hl(s[j0][0], s[j0][1], pal[ks][0]);
            pah[ks][1] = pack_hl(s[j0][2], s[j0][3], pal[ks][1]);
            pah[ks][2] = pack_hl(s[j1][0], s[j1][1], pal[ks][2]);
            pah[ks][3] = pack_hl(s[j1][2], s[j1][3], pal[ks][3]);
        }

        // ---- O += P @ V, 2-term (split P, single V) ----
        #pragma unroll
        for (int ks = 0; ks < 4; ks++) {
            uint32_t vh[4][4];
            #pragma unroll
            for (int d = 0; d < 4; d++) {
                uint32_t voff = SW128((ks * 16 + v_r) * 128 + d * 32 + v_nb);
                LDMATRIX_X4_T(vh[d][0], vh[d][1], vh[d][2], vh[d][3],
                              stg + 8192 + voff);
            }
            #pragma unroll
            for (int d = 0; d < 4; d++) {
                MMA_F16(o[2*d][0], o[2*d][1], o[2*d][2], o[2*d][3],
                        pah[ks][0], pah[ks][1], pah[ks][2], pah[ks][3], vh[d][0], vh[d][1]);
                MMA_F16(o[2*d+1][0], o[2*d+1][1], o[2*d+1][2], o[2*d+1][3],
                        pah[ks][0], pah[ks][1], pah[ks][2], pah[ks][3], vh[d][2], vh[d][3]);
            }
            #pragma unroll
            for (int d = 0; d < 4; d++) {
                MMA_F16(o[2*d][0], o[2*d][1], o[2*d][2], o[2*d][3],
                        pal[ks][0], pal[ks][1], pal[ks][2], pal[ks][3], vh[d][0], vh[d][1]);
                MMA_F16(o[2*d+1][0], o[2*d+1][1], o[2*d+1][2], o[2*d+1][3],
                        pal[ks][0], pal[ks][1], pal[ks][2], pal[ks][3], vh[d][2], vh[d][3]);
            }
        }
        __syncthreads();
    }

    // ---- epilogue: normalize, split hi/lo, write [token][h*64+dim] ----
    const float inv0 = 1.f / l0;
    const float inv1 = 1.f / l1;
    const int r0 = tok0 + wid * 16 + g;
    const int r1 = r0 + 8;
    #pragma unroll
    for (int j = 0; j < 8; j++) {
        const int col = h * HDIM + j * 8 + tq * 2;
        uint32_t lo0, lo1;
        uint32_t hi0 = pack_hl(o[j][0] * inv0, o[j][1] * inv0, lo0);
        uint32_t hi1 = pack_hl(o[j][2] * inv1, o[j][3] * inv1, lo1);
        *(uint32_t*)(oh + (size_t)r0 * EMB + col) = hi0;
        *(uint32_t*)(ol + (size_t)r0 * EMB + col) = lo0;
        *(uint32_t*)(oh + (size_t)r1 * EMB + col) = hi1;
        *(uint32_t*)(ol + (size_t)r1 * EMB + col) = lo1;
    }
}

// ---------------------------------------------------------------------------
extern "C" void kernel_launch(void* const* d_in, const int* in_sizes, int n_in,
                              void* d_out, int out_size)
{
    const float* x     = (const float*)d_in[0];
    const float* w_qkv = (const float*)d_in[1];
    const float* w_out = (const float*)d_in[2];
    const float* b_out = (const float*)d_in[3];
    const int*   mask  = (const int*)  d_in[4];
    float* out = (float*)d_out;

    __half *xh, *xl, *wqh, *woh, *wol, *qkh, *qkl, *ath, *atl;
    cudaGetSymbolAddress((void**)&xh,  g_xh);
    cudaGetSymbolAddress((void**)&xl,  g_xl);
    cudaGetSymbolAddress((void**)&wqh, g_wqkvh);
    cudaGetSymbolAddress((void**)&woh, g_wouth);
    cudaGetSymbolAddress((void**)&wol, g_woutl);
    cudaGetSymbolAddress((void**)&qkh, g_qkvh);
    cudaGetSymbolAddress((void**)&qkl, g_qkvl);
    cudaGetSymbolAddress((void**)&ath, g_atth);
    cudaGetSymbolAddress((void**)&atl, g_attl);

    cudaFuncSetAttribute((const void*)gemm_2t_kernel,
                         cudaFuncAttributeMaxDynamicSharedMemorySize, G2_SMEM);
    cudaFuncSetAttribute((const void*)gemm_3t_kernel,
                         cudaFuncAttributeMaxDynamicSharedMemorySize, G3_SMEM);
    cudaFuncSetAttribute((const void*)flash_mma_kernel,
                         cudaFuncAttributeMaxDynamicSharedMemorySize, FA_SMEM);

    // 0) conversions
    {
        int n4 = TOK * EMB / 4;
        split_kernel<<<(n4 + 255) / 256, 256>>>((const float4*)x, xh, xl, n4);
        n4 = QKVF * EMB / 4;
        tohalf_kernel<<<(n4 + 255) / 256, 256>>>((const float4*)w_qkv, wqh, n4);
        n4 = EMB * EMB / 4;
        split_kernel<<<(n4 + 255) / 256, 256>>>((const float4*)w_out, woh, wol, n4);
    }

    // 1) QKV projection, 2-term -> fp16 hi/lo qkv
    {
        dim3 grid(QKVF / 128, TOK / 128);
        gemm_2t_kernel<<<grid, 256, G2_SMEM>>>(xh, xl, wqh, qkh, qkl,
                                               TOK, QKVF, EMB);
    }

    // 2) Flash attention, 2-term -> fp16 hi/lo attn
    {
        dim3 grid(SEQ / 128, HEADS, BATCH);
        flash_mma_kernel<<<grid, 256, FA_SMEM>>>(qkh, qkl, mask, ath, atl);
    }

    // 3) Output projection, 3-term + bias -> f32 out
    {
        dim3 grid(EMB / 128, TOK / 128);
        gemm_3t_kernel<<<grid, 256, G3_SMEM>>>(ath, atl, woh, wol, b_out, out,
                                               TOK, EMB, EMB);
    }
}

// round 7
// speedup vs baseline: 1.1181x; 1.1181x over previous
#include <cuda_runtime.h>
#include <cuda_bf16.h>
#include <math.h>
#include <stdint.h>

// Problem constants
#define BATCH 4
#define SEQ   2048
#define EMB   1024
#define HEADS 16
#define HDIM  64
#define TOK   (BATCH * SEQ)          // 8192
#define QKVF  (3 * EMB)              // 3072

// Scratch (device globals — no allocation allowed)
__device__ __nv_bfloat16 g_xh[(size_t)TOK * EMB];
__device__ __nv_bfloat16 g_xl[(size_t)TOK * EMB];
__device__ __nv_bfloat16 g_wqkvh[(size_t)QKVF * EMB];
__device__ __nv_bfloat16 g_wqkvl[(size_t)QKVF * EMB];
__device__ __nv_bfloat16 g_wouth[(size_t)EMB * EMB];
__device__ __nv_bfloat16 g_woutl[(size_t)EMB * EMB];
__device__ __nv_bfloat16 g_qkvh[(size_t)TOK * QKVF];
__device__ __nv_bfloat16 g_qkvl[(size_t)TOK * QKVF];
__device__ __nv_bfloat16 g_atth[(size_t)TOK * EMB];
__device__ __nv_bfloat16 g_attl[(size_t)TOK * EMB];

// ---------------------------------------------------------------------------
// PTX helpers — only sm_80+ features (compute_103 baseline safe)
// ---------------------------------------------------------------------------
__device__ __forceinline__ uint32_t smem_u32(const void* p) {
    uint32_t a;
    asm("{ .reg .u64 t; cvta.to.shared.u64 t, %1; cvt.u32.u64 %0, t; }"
        : "=r"(a) : "l"(p));
    return a;
}

#define CP_ASYNC16(dst, src) \
    asm volatile("cp.async.cg.shared.global [%0], [%1], 16;" :: "r"(dst), "l"(src))
#define CP_COMMIT() asm volatile("cp.async.commit_group;")
#define CP_WAIT(n)  asm volatile("cp.async.wait_group %0;" :: "n"(n))

#define LDMATRIX_X4(r0, r1, r2, r3, addr) \
    asm volatile("ldmatrix.sync.aligned.m8n8.x4.shared.b16 {%0,%1,%2,%3}, [%4];" \
                 : "=r"(r0), "=r"(r1), "=r"(r2), "=r"(r3) : "r"(addr))
#define LDMATRIX_X4_T(r0, r1, r2, r3, addr) \
    asm volatile("ldmatrix.sync.aligned.m8n8.x4.trans.shared.b16 {%0,%1,%2,%3}, [%4];" \
                 : "=r"(r0), "=r"(r1), "=r"(r2), "=r"(r3) : "r"(addr))

#define MMA_BF16(c0, c1, c2, c3, a0, a1, a2, a3, b0, b1) \
    asm volatile("mma.sync.aligned.m16n8k16.row.col.f32.bf16.bf16.f32 " \
                 "{%0,%1,%2,%3}, {%4,%5,%6,%7}, {%8,%9}, {%0,%1,%2,%3};" \
                 : "+f"(c0), "+f"(c1), "+f"(c2), "+f"(c3) \
                 : "r"(a0), "r"(a1), "r"(a2), "r"(a3), "r"(b0), "r"(b1))

__device__ __forceinline__ float ex2f(float x) {
    float y;
    asm("ex2.approx.f32 %0, %1;" : "=f"(y) : "f"(x));
    return y;
}

__device__ __forceinline__ uint32_t pack_hi_lo(float a, float b, uint32_t& lo) {
    __nv_bfloat162 h = __floats2bfloat162_rn(a, b);
    float ra = a - __bfloat162float(h.x);
    float rb = b - __bfloat162float(h.y);
    __nv_bfloat162 r = __floats2bfloat162_rn(ra, rb);
    lo = reinterpret_cast<uint32_t&>(r);
    return reinterpret_cast<uint32_t&>(h);
}

// SW128 XOR swizzle on byte offsets (rows of 128B): conflict-free ldmatrix
#define SW128(off) ((uint32_t)(off) ^ ((((uint32_t)(off)) >> 3) & 0x70))

// ---------------------------------------------------------------------------
// fp32 -> bf16 hi/lo split
// ---------------------------------------------------------------------------
__global__ void __launch_bounds__(256) split_kernel(
    const float4* __restrict__ in, __nv_bfloat16* __restrict__ hi,
    __nv_bfloat16* __restrict__ lo, int n4)
{
    int i = blockIdx.x * blockDim.x + threadIdx.x;
    if (i >= n4) return;
    float4 v = in[i];
    float f[4] = {v.x, v.y, v.z, v.w};
    __nv_bfloat16 h[4], l[4];
    #pragma unroll
    for (int j = 0; j < 4; j++) {
        h[j] = __float2bfloat16(f[j]);
        l[j] = __float2bfloat16(f[j] - __bfloat162float(h[j]));
    }
    ((uint2*)hi)[i] = *(uint2*)h;
    ((uint2*)lo)[i] = *(uint2*)l;
}

// ---------------------------------------------------------------------------
// mma.sync GEMM:  C[M,N] = A[M,K] * B[N,K]^T (+ bias[N])
// bf16 hi/lo 3-term, fp32 accum. CTA 128x128, BK=32, 8 warps (2x4).
// SW128-swizzled smem rows: [32 hi bf16 | 32 lo bf16] = 128B.
// 3-stage cp.async pipeline; mi-PAIR interleaved MMAs (8-deep acc ILP).
// ---------------------------------------------------------------------------
#define BM 128
#define BN 128
#define BK 32
#define TILE_B (128 * 128)          // 16 KB: combined hi|lo tile
#define STAGE_B (2 * TILE_B)        // A + B = 32 KB
#define OFF_A 0
#define OFF_B TILE_B
#define GM_SMEM (3 * STAGE_B)       // 98304

template <bool BIAS, bool SPLIT>
__global__ void __launch_bounds__(256, 2) gemm_mma_kernel(
    const __nv_bfloat16* __restrict__ Ah, const __nv_bfloat16* __restrict__ Al,
    const __nv_bfloat16* __restrict__ Bh, const __nv_bfloat16* __restrict__ Bl,
    const float* __restrict__ bias, float* __restrict__ C,
    __nv_bfloat16* __restrict__ Ch, __nv_bfloat16* __restrict__ Cl,
    int M, int N, int K)
{
    extern __shared__ char sm[];
    const uint32_t smb = smem_u32(sm);
    const int tid  = threadIdx.x;
    const int wid  = tid >> 5;
    const int lane = tid & 31;
    const int m0 = blockIdx.y * BM;
    const int n0 = blockIdx.x * BN;
    const int wm = (wid >> 2) * 64;
    const int wn = (wid & 3) * 32;

    const char* Ahc = (const char*)Ah;
    const char* Alc = (const char*)Al;
    const char* Bhc = (const char*)Bh;
    const char* Blc = (const char*)Bl;

    auto load_chunk = [&](int k0, int stg) {
        const uint32_t sb = smb + stg * STAGE_B;
        #pragma unroll
        for (int i = 0; i < 4; i++) {
            int idx = tid + i * 256;           // 0..1023
            int r = idx >> 3;                  // 0..127
            int c = (idx & 7) * 16;            // 0..112
            uint32_t so = SW128(r * 128 + c);
            size_t gA = ((size_t)(m0 + r) * K + k0) * 2;
            size_t gB = ((size_t)(n0 + r) * K + k0) * 2;
            const char* sA = (c < 64) ? (Ahc + gA + c) : (Alc + gA + c - 64);
            const char* sB = (c < 64) ? (Bhc + gB + c) : (Blc + gB + c - 64);
            CP_ASYNC16(sb + OFF_A + so, sA);
            CP_ASYNC16(sb + OFF_B + so, sB);
        }
    };

    float acc[4][4][4];
    #pragma unroll
    for (int i = 0; i < 4; i++)
        #pragma unroll
        for (int j = 0; j < 4; j++)
            #pragma unroll
            for (int c = 0; c < 4; c++) acc[i][j][c] = 0.f;

    const int nch = K / BK;
    load_chunk(0, 0); CP_COMMIT();
    load_chunk(BK, 1); CP_COMMIT();

    const int a_row  = lane & 15;
    const int a_kofb = (lane >> 4) * 16;
    const int bq     = lane >> 3;
    const int b_row  = (bq >> 1) * 8 + (lane & 7);
    const int b_kofb = (bq & 1) * 16;

    int stg = 0;
    for (int ch = 0; ch < nch; ch++) {
        CP_WAIT(1);
        __syncthreads();
        if (ch + 2 < nch) {
            int s2 = stg + 2; if (s2 >= 3) s2 -= 3;
            load_chunk((ch + 2) * BK, s2);
        }
        CP_COMMIT();

        const uint32_t sb = smb + stg * STAGE_B;
        #pragma unroll
        for (int ks = 0; ks < 2; ks++) {
            const int kb = ks * 32;            // byte col of k-step
            uint32_t bh[4][2], bl[4][2];
            #pragma unroll
            for (int p = 0; p < 2; p++) {
                uint32_t row = (wn + p * 16 + b_row) * 128;
                LDMATRIX_X4(bh[2*p][0], bh[2*p][1], bh[2*p+1][0], bh[2*p+1][1],
                            sb + OFF_B + SW128(row + kb + b_kofb));
                LDMATRIX_X4(bl[2*p][0], bl[2*p][1], bl[2*p+1][0], bl[2*p+1][1],
                            sb + OFF_B + SW128(row + 64 + kb + b_kofb));
            }
            // mi pairs: 8 independent MMAs between accumulator reuse
            #pragma unroll
            for (int mp = 0; mp < 2; mp++) {
                uint32_t ah[2][4], al[2][4];
                #pragma unroll
                for (int q = 0; q < 2; q++) {
                    int mi = mp * 2 + q;
                    uint32_t row = (wm + mi * 16 + a_row) * 128;
                    LDMATRIX_X4(ah[q][0], ah[q][1], ah[q][2], ah[q][3],
                                sb + OFF_A + SW128(row + kb + a_kofb));
                    LDMATRIX_X4(al[q][0], al[q][1], al[q][2], al[q][3],
                                sb + OFF_A + SW128(row + 64 + kb + a_kofb));
                }
                #pragma unroll
                for (int q = 0; q < 2; q++) {
                    int mi = mp * 2 + q;
                    #pragma unroll
                    for (int nj = 0; nj < 4; nj++)
                        MMA_BF16(acc[mi][nj][0], acc[mi][nj][1], acc[mi][nj][2], acc[mi][nj][3],
                                 ah[q][0], ah[q][1], ah[q][2], ah[q][3], bh[nj][0], bh[nj][1]);
                }
                #pragma unroll
                for (int q = 0; q < 2; q++) {
                    int mi = mp * 2 + q;
                    #pragma unroll
                    for (int nj = 0; nj < 4; nj++)
                        MMA_BF16(acc[mi][nj][0], acc[mi][nj][1], acc[mi][nj][2], acc[mi][nj][3],
                                 ah[q][0], ah[q][1], ah[q][2], ah[q][3], bl[nj][0], bl[nj][1]);
                }
                #pragma unroll
                for (int q = 0; q < 2; q++) {
                    int mi = mp * 2 + q;
                    #pragma unroll
                    for (int nj = 0; nj < 4; nj++)
                        MMA_BF16(acc[mi][nj][0], acc[mi][nj][1], acc[mi][nj][2], acc[mi][nj][3],
                                 al[q][0], al[q][1], al[q][2], al[q][3], bh[nj][0], bh[nj][1]);
                }
            }
        }
        if (++stg == 3) stg = 0;
    }

    const int g = lane >> 2, t = lane & 3;
    #pragma unroll
    for (int mi = 0; mi < 4; mi++) {
        const int row = m0 + wm + mi * 16 + g;
        #pragma unroll
        for (int nj = 0; nj < 4; nj++) {
            const int col = n0 + wn + nj * 8 + t * 2;
            if (SPLIT) {
                uint32_t lo0, lo1;
                uint32_t hi0 = pack_hi_lo(acc[mi][nj][0], acc[mi][nj][1], lo0);
                uint32_t hi1 = pack_hi_lo(acc[mi][nj][2], acc[mi][nj][3], lo1);
                *(uint32_t*)(Ch + (size_t)row * N + col)       = hi0;
                *(uint32_t*)(Cl + (size_t)row * N + col)       = lo0;
                *(uint32_t*)(Ch + (size_t)(row + 8) * N + col) = hi1;
                *(uint32_t*)(Cl + (size_t)(row + 8) * N + col) = lo1;
            } else {
                float b0 = 0.f, b1 = 0.f;
                if (BIAS) { b0 = bias[col]; b1 = bias[col + 1]; }
                float2 v0 = {acc[mi][nj][0] + b0, acc[mi][nj][1] + b1};
                float2 v1 = {acc[mi][nj][2] + b0, acc[mi][nj][3] + b1};
                *(float2*)(C + (size_t)row * N + col)       = v0;
                *(float2*)(C + (size_t)(row + 8) * N + col) = v1;
            }
        }
    }
}

// ---------------------------------------------------------------------------
// Flash attention with mma.sync (bf16 hi/lo 3-term, fp32 softmax/accum)
// grid (SEQ/128, HEADS, BATCH), 256 threads. SW128-swizzled smem, 2 CTAs/SM.
// ---------------------------------------------------------------------------
#define FA_OFF_QH 0
#define FA_OFF_QL 16384
#define FA_OFF_KV 32768
#define FA_KH 0
#define FA_KL 8192
#define FA_VH 16384
#define FA_VL 24576
#define FA_STAGE 32768
#define FA_OFF_MADD (FA_OFF_KV + 2 * FA_STAGE)   // 98304
#define FA_SMEM (FA_OFF_MADD + 2 * 64 * 4)       // 98816
#define FA_C1 0.18033688011112042f               // 0.125 * log2(e)

__global__ void __launch_bounds__(256, 2) flash_mma_kernel(
    const __nv_bfloat16* __restrict__ qkh, const __nv_bfloat16* __restrict__ qkl,
    const int* __restrict__ mask,
    __nv_bfloat16* __restrict__ oh, __nv_bfloat16* __restrict__ ol)
{
    extern __shared__ char sm[];
    const uint32_t smb = smem_u32(sm);
    const int tid = threadIdx.x, wid = tid >> 5, lane = tid & 31;
    const int qb = blockIdx.x, h = blockIdx.y, b = blockIdx.z;
    const int tok0 = b * SEQ + qb * 128;

    const char* qkhc = (const char*)qkh;
    const char* qklc = (const char*)qkl;

    auto load_kv = [&](int ch) {
        const uint32_t stg = smb + FA_OFF_KV + (ch & 1) * FA_STAGE;
        const int k0 = ch * 64;
        #pragma unroll
        for (int i = 0; i < 8; i++) {
            int idx = tid + i * 256;                 // 0..2047
            int tile = idx >> 9;                     // 0..3: KH,KL,VH,VL
            int r = (idx >> 3) & 63;
            int c = (idx & 7) * 16;
            size_t gK = ((size_t)(b * SEQ + k0 + r) * QKVF + EMB + h * HDIM) * 2 + c;
            size_t gV = gK + (size_t)EMB * 2;
            const char* src;
            if      (tile == 0) src = qkhc + gK;
            else if (tile == 1) src = qklc + gK;
            else if (tile == 2) src = qkhc + gV;
            else                src = qklc + gV;
            CP_ASYNC16(stg + tile * 8192 + SW128(r * 128 + c), src);
        }
        if (tid < 64) {
            float* md = (float*)(sm + FA_OFF_MADD) + (ch & 1) * 64;
            md[tid] = mask[b * SEQ + k0 + tid] ? 0.f : -1e9f;
        }
    };

    #pragma unroll
    for (int i = 0; i < 8; i++) {
        int idx = tid + i * 256;                     // 0..2047
        int t2 = idx >> 10;                          // 0 = hi, 1 = lo
        int r  = (idx >> 3) & 127;
        int c  = (idx & 7) * 16;
        size_t gb = ((size_t)(tok0 + r) * QKVF + h * HDIM) * 2 + c;
        const char* src = (t2 ? qklc : qkhc) + gb;
        CP_ASYNC16(smb + (t2 ? FA_OFF_QL : FA_OFF_QH) + SW128(r * 128 + c), src);
    }
    load_kv(0);
    CP_COMMIT();

    const int g  = lane >> 2, tq = lane & 3;
    const int a_row = lane & 15, a_kb = (lane >> 4) * 16;
    const int bq = lane >> 3;
    const int b_r = (bq >> 1) * 8 + (lane & 7), b_kb = (bq & 1) * 16;
    const int v_r = (bq & 1) * 8 + (lane & 7),  v_nb = (bq >> 1) * 16;

    float m0r = -1e30f, m1r = -1e30f, l0 = 0.f, l1 = 0.f;
    float o[8][4];
    #pragma unroll
    for (int j = 0; j < 8; j++)
        #pragma unroll
        for (int c = 0; c < 4; c++) o[j][c] = 0.f;

    const int NCH = SEQ / 64;
    for (int ch = 0; ch < NCH; ch++) {
        if (ch + 1 < NCH) { load_kv(ch + 1); CP_COMMIT(); CP_WAIT(1); }
        else              { CP_WAIT(0); }
        __syncthreads();
        const uint32_t stg = smb + FA_OFF_KV + (ch & 1) * FA_STAGE;

        float s[8][4];
        #pragma unroll
        for (int j = 0; j < 8; j++)
            #pragma unroll
            for (int c = 0; c < 4; c++) s[j][c] = 0.f;

        #pragma unroll
        for (int ks = 0; ks < 4; ks++) {
            const int kb = ks * 32;
            uint32_t qh[4], ql[4];
            uint32_t qrow = (wid * 16 + a_row) * 128;
            LDMATRIX_X4(qh[0], qh[1], qh[2], qh[3],
                        smb + FA_OFF_QH + SW128(qrow + kb + a_kb));
            LDMATRIX_X4(ql[0], ql[1], ql[2], ql[3],
                        smb + FA_OFF_QL + SW128(qrow + kb + a_kb));
            uint32_t kh[8][2], kl[8][2];
            #pragma unroll
            for (int p = 0; p < 4; p++) {
                uint32_t krow = (p * 16 + b_r) * 128;
                LDMATRIX_X4(kh[2*p][0], kh[2*p][1], kh[2*p+1][0], kh[2*p+1][1],
                            stg + FA_KH + SW128(krow + kb + b_kb));
                LDMATRIX_X4(kl[2*p][0], kl[2*p][1], kl[2*p+1][0], kl[2*p+1][1],
                            stg + FA_KL + SW128(krow + kb + b_kb));
            }
            #pragma unroll
            for (int j = 0; j < 8; j++)
                MMA_BF16(s[j][0], s[j][1], s[j][2], s[j][3],
                         qh[0], qh[1], qh[2], qh[3], kh[j][0], kh[j][1]);
            #pragma unroll
            for (int j = 0; j < 8; j++)
                MMA_BF16(s[j][0], s[j][1], s[j][2], s[j][3],
                         qh[0], qh[1], qh[2], qh[3], kl[j][0], kl[j][1]);
            #pragma unroll
            for (int j = 0; j < 8; j++)
                MMA_BF16(s[j][0], s[j][1], s[j][2], s[j][3],
                         ql[0], ql[1], ql[2], ql[3], kh[j][0], kh[j][1]);
        }

        const float* md = (const float*)(sm + FA_OFF_MADD) + (ch & 1) * 64;
        #pragma unroll
        for (int j = 0; j < 8; j++) {
            float m0 = md[j * 8 + tq * 2];
            float m1 = md[j * 8 + tq * 2 + 1];
            s[j][0] = fmaf(s[j][0], FA_C1, m0);
            s[j][1] = fmaf(s[j][1], FA_C1, m1);
            s[j][2] = fmaf(s[j][2], FA_C1, m0);
            s[j][3] = fmaf(s[j][3], FA_C1, m1);
        }
        float rm0 = -1e30f, rm1 = -1e30f;
        #pragma unroll
        for (int j = 0; j < 8; j++) {
            rm0 = fmaxf(rm0, fmaxf(s[j][0], s[j][1]));
            rm1 = fmaxf(rm1, fmaxf(s[j][2], s[j][3]));
        }
        rm0 = fmaxf(rm0, __shfl_xor_sync(0xffffffffu, rm0, 1));
        rm0 = fmaxf(rm0, __shfl_xor_sync(0xffffffffu, rm0, 2));
        rm1 = fmaxf(rm1, __shfl_xor_sync(0xffffffffu, rm1, 1));
        rm1 = fmaxf(rm1, __shfl_xor_sync(0xffffffffu, rm1, 2));
        const float mn0 = fmaxf(m0r, rm0);
        const float mn1 = fmaxf(m1r, rm1);
        const float al0 = ex2f(m0r - mn0);
        const float al1 = ex2f(m1r - mn1);
        m0r = mn0; m1r = mn1;

        float rs0 = 0.f, rs1 = 0.f;
        #pragma unroll
        for (int j = 0; j < 8; j++) {
            s[j][0] = ex2f(s[j][0] - mn0);
            s[j][1] = ex2f(s[j][1] - mn0);
            s[j][2] = ex2f(s[j][2] - mn1);
            s[j][3] = ex2f(s[j][3] - mn1);
            rs0 += s[j][0] + s[j][1];
            rs1 += s[j][2] + s[j][3];
        }
        rs0 += __shfl_xor_sync(0xffffffffu, rs0, 1);
        rs0 += __shfl_xor_sync(0xffffffffu, rs0, 2);
        rs1 += __shfl_xor_sync(0xffffffffu, rs1, 1);
        rs1 += __shfl_xor_sync(0xffffffffu, rs1, 2);
        l0 = l0 * al0 + rs0;
        l1 = l1 * al1 + rs1;

        #pragma unroll
        for (int j = 0; j < 8; j++) {
            o[j][0] *= al0; o[j][1] *= al0;
            o[j][2] *= al1; o[j][3] *= al1;
        }

        uint32_t pah[4][4], pal[4][4];
        #pragma unroll
        for (int ks = 0; ks < 4; ks++) {
            const int j0 = 2 * ks, j1 = 2 * ks + 1;
            pah[ks][0] = pack_hi_lo(s[j0][0], s[j0][1], pal[ks][0]);
            pah[ks][1] = pack_hi_lo(s[j0][2], s[j0][3], pal[ks][1]);
            pah[ks][2] = pack_hi_lo(s[j1][0], s[j1][1], pal[ks][2]);
            pah[ks][3] = pack_hi_lo(s[j1][2], s[j1][3], pal[ks][3]);
        }

        #pragma unroll
        for (int ks = 0; ks < 4; ks++) {
            uint32_t vh[4][4], vl[4][4];
            #pragma unroll
            for (int d = 0; d < 4; d++) {
                uint32_t voff = SW128((ks * 16 + v_r) * 128 + d * 32 + v_nb);
                LDMATRIX_X4_T(vh[d][0], vh[d][1], vh[d][2], vh[d][3], stg + FA_VH + voff);
                LDMATRIX_X4_T(vl[d][0], vl[d][1], vl[d][2], vl[d][3], stg + FA_VL + voff);
            }
            #pragma unroll
            for (int d = 0; d < 4; d++) {
                MMA_BF16(o[2*d][0], o[2*d][1], o[2*d][2], o[2*d][3],
                         pah[ks][0], pah[ks][1], pah[ks][2], pah[ks][3], vh[d][0], vh[d][1]);
                MMA_BF16(o[2*d+1][0], o[2*d+1][1], o[2*d+1][2], o[2*d+1][3],
                         pah[ks][0], pah[ks][1], pah[ks][2], pah[ks][3], vh[d][2], vh[d][3]);
            }
            #pragma unroll
            for (int d = 0; d < 4; d++) {
                MMA_BF16(o[2*d][0], o[2*d][1], o[2*d][2], o[2*d][3],
                         pah[ks][0], pah[ks][1], pah[ks][2], pah[ks][3], vl[d][0], vl[d][1]);
                MMA_BF16(o[2*d+1][0], o[2*d+1][1], o[2*d+1][2], o[2*d+1][3],
                         pah[ks][0], pah[ks][1], pah[ks][2], pah[ks][3], vl[d][2], vl[d][3]);
            }
            #pragma unroll
            for (int d = 0; d < 4; d++) {
                MMA_BF16(o[2*d][0], o[2*d][1], o[2*d][2], o[2*d][3],
                         pal[ks][0], pal[ks][1], pal[ks][2], pal[ks][3], vh[d][0], vh[d][1]);
                MMA_BF16(o[2*d+1][0], o[2*d+1][1], o[2*d+1][2], o[2*d+1][3],
                         pal[ks][0], pal[ks][1], pal[ks][2], pal[ks][3], vh[d][2], vh[d][3]);
            }
        }
        __syncthreads();
    }

    const float inv0 = 1.f / l0;
    const float inv1 = 1.f / l1;
    const int r0 = tok0 + wid * 16 + g;
    const int r1 = r0 + 8;
    #pragma unroll
    for (int j = 0; j < 8; j++) {
        const int col = h * HDIM + j * 8 + tq * 2;
        uint32_t lo0, lo1;
        uint32_t hi0 = pack_hi_lo(o[j][0] * inv0, o[j][1] * inv0, lo0);
        uint32_t hi1 = pack_hi_lo(o[j][2] * inv1, o[j][3] * inv1, lo1);
        *(uint32_t*)(oh + (size_t)r0 * EMB + col) = hi0;
        *(uint32_t*)(ol + (size_t)r0 * EMB + col) = lo0;
        *(uint32_t*)(oh + (size_t)r1 * EMB + col) = hi1;
        *(uint32_t*)(ol + (size_t)r1 * EMB + col) = lo1;
    }
}

// ---------------------------------------------------------------------------
extern "C" void kernel_launch(void* const* d_in, const int* in_sizes, int n_in,
                              void* d_out, int out_size)
{
    const float* x     = (const float*)d_in[0];
    const float* w_qkv = (const float*)d_in[1];
    const float* w_out = (const float*)d_in[2];
    const float* b_out = (const float*)d_in[3];
    const int*   mask  = (const int*)  d_in[4];
    float* out = (float*)d_out;

    __nv_bfloat16 *xh, *xl, *wqh, *wql, *woh, *wol, *qkh, *qkl, *ath, *atl;
    cudaGetSymbolAddress((void**)&xh,  g_xh);
    cudaGetSymbolAddress((void**)&xl,  g_xl);
    cudaGetSymbolAddress((void**)&wqh, g_wqkvh);
    cudaGetSymbolAddress((void**)&wql, g_wqkvl);
    cudaGetSymbolAddress((void**)&woh, g_wouth);
    cudaGetSymbolAddress((void**)&wol, g_woutl);
    cudaGetSymbolAddress((void**)&qkh, g_qkvh);
    cudaGetSymbolAddress((void**)&qkl, g_qkvl);
    cudaGetSymbolAddress((void**)&ath, g_atth);
    cudaGetSymbolAddress((void**)&atl, g_attl);

    cudaFuncSetAttribute((const void*)gemm_mma_kernel<false, true>,
                         cudaFuncAttributeMaxDynamicSharedMemorySize, GM_SMEM);
    cudaFuncSetAttribute((const void*)gemm_mma_kernel<true, false>,
                         cudaFuncAttributeMaxDynamicSharedMemorySize, GM_SMEM);
    cudaFuncSetAttribute((const void*)flash_mma_kernel,
                         cudaFuncAttributeMaxDynamicSharedMemorySize, FA_SMEM);

    // 0) splits
    {
        int n4 = TOK * EMB / 4;
        split_kernel<<<(n4 + 255) / 256, 256>>>((const float4*)x, xh, xl, n4);
        n4 = QKVF * EMB / 4;
        split_kernel<<<(n4 + 255) / 256, 256>>>((const float4*)w_qkv, wqh, wql, n4);
        n4 = EMB * EMB / 4;
        split_kernel<<<(n4 + 255) / 256, 256>>>((const float4*)w_out, woh, wol, n4);
    }

    // 1) QKV projection -> bf16 hi/lo qkv
    {
        dim3 grid(QKVF / BN, TOK / BM);
        gemm_mma_kernel<false, true><<<grid, 256, GM_SMEM>>>(
            xh, xl, wqh, wql, nullptr, nullptr, qkh, qkl, TOK, QKVF, EMB);
    }

    // 2) Flash attention -> bf16 hi/lo attn
    {
        dim3 grid(SEQ / 128, HEADS, BATCH);
        flash_mma_kernel<<<grid, 256, FA_SMEM>>>(qkh, qkl, mask, ath, atl);
    }

    // 3) Output projection + bias -> f32 out
    {
        dim3 grid(EMB / BN, TOK / BM);
        gemm_mma_kernel<true, false><<<grid, 256, GM_SMEM>>>(
            ath, atl, woh, wol, b_out, out, nullptr, nullptr, TOK, EMB, EMB);
    }
}

// round 8
// speedup vs baseline: 1.2253x; 1.0958x over previous
#include <cuda_runtime.h>
#include <cuda_bf16.h>
#include <math.h>
#include <stdint.h>

// Problem constants
#define BATCH 4
#define SEQ   2048
#define EMB   1024
#define HEADS 16
#define HDIM  64
#define TOK   (BATCH * SEQ)          // 8192
#define QKVF  (3 * EMB)              // 3072

// Scratch (device globals — no allocation allowed)
__device__ __nv_bfloat16 g_xh[(size_t)TOK * EMB];
__device__ __nv_bfloat16 g_xl[(size_t)TOK * EMB];
__device__ __nv_bfloat16 g_wqkvh[(size_t)QKVF * EMB];
__device__ __nv_bfloat16 g_wqkvl[(size_t)QKVF * EMB];
__device__ __nv_bfloat16 g_wouth[(size_t)EMB * EMB];
__device__ __nv_bfloat16 g_woutl[(size_t)EMB * EMB];
__device__ __nv_bfloat16 g_qkvh[(size_t)TOK * QKVF];
__device__ __nv_bfloat16 g_qkvl[(size_t)TOK * QKVF];
__device__ __nv_bfloat16 g_atth[(size_t)TOK * EMB];
__device__ __nv_bfloat16 g_attl[(size_t)TOK * EMB];

// ---------------------------------------------------------------------------
// PTX helpers — only sm_80+ features (compute_103 baseline safe)
// ---------------------------------------------------------------------------
__device__ __forceinline__ uint32_t smem_u32(const void* p) {
    uint32_t a;
    asm("{ .reg .u64 t; cvta.to.shared.u64 t, %1; cvt.u32.u64 %0, t; }"
        : "=r"(a) : "l"(p));
    return a;
}

#define CP_ASYNC16(dst, src) \
    asm volatile("cp.async.cg.shared.global [%0], [%1], 16;" :: "r"(dst), "l"(src))
#define CP_COMMIT() asm volatile("cp.async.commit_group;")
#define CP_WAIT(n)  asm volatile("cp.async.wait_group %0;" :: "n"(n))

#define LDMATRIX_X4(r0, r1, r2, r3, addr) \
    asm volatile("ldmatrix.sync.aligned.m8n8.x4.shared.b16 {%0,%1,%2,%3}, [%4];" \
                 : "=r"(r0), "=r"(r1), "=r"(r2), "=r"(r3) : "r"(addr))
#define LDMATRIX_X4_T(r0, r1, r2, r3, addr) \
    asm volatile("ldmatrix.sync.aligned.m8n8.x4.trans.shared.b16 {%0,%1,%2,%3}, [%4];" \
                 : "=r"(r0), "=r"(r1), "=r"(r2), "=r"(r3) : "r"(addr))

#define MMA_BF16(c0, c1, c2, c3, a0, a1, a2, a3, b0, b1) \
    asm volatile("mma.sync.aligned.m16n8k16.row.col.f32.bf16.bf16.f32 " \
                 "{%0,%1,%2,%3}, {%4,%5,%6,%7}, {%8,%9}, {%0,%1,%2,%3};" \
                 : "+f"(c0), "+f"(c1), "+f"(c2), "+f"(c3) \
                 : "r"(a0), "r"(a1), "r"(a2), "r"(a3), "r"(b0), "r"(b1))

__device__ __forceinline__ float ex2f(float x) {
    float y;
    asm("ex2.approx.f32 %0, %1;" : "=f"(y) : "f"(x));
    return y;
}

__device__ __forceinline__ uint32_t pack_hi_lo(float a, float b, uint32_t& lo) {
    __nv_bfloat162 h = __floats2bfloat162_rn(a, b);
    float ra = a - __bfloat162float(h.x);
    float rb = b - __bfloat162float(h.y);
    __nv_bfloat162 r = __floats2bfloat162_rn(ra, rb);
    lo = reinterpret_cast<uint32_t&>(r);
    return reinterpret_cast<uint32_t&>(h);
}

// SW128 XOR swizzle on byte offsets (rows of 128B): conflict-free ldmatrix
#define SW128(off) ((uint32_t)(off) ^ ((((uint32_t)(off)) >> 3) & 0x70))

// ---------------------------------------------------------------------------
// fp32 -> bf16 hi/lo split
// ---------------------------------------------------------------------------
__global__ void __launch_bounds__(256) split_kernel(
    const float4* __restrict__ in, __nv_bfloat16* __restrict__ hi,
    __nv_bfloat16* __restrict__ lo, int n4)
{
    int i = blockIdx.x * blockDim.x + threadIdx.x;
    if (i >= n4) return;
    float4 v = in[i];
    float f[4] = {v.x, v.y, v.z, v.w};
    __nv_bfloat16 h[4], l[4];
    #pragma unroll
    for (int j = 0; j < 4; j++) {
        h[j] = __float2bfloat16(f[j]);
        l[j] = __float2bfloat16(f[j] - __bfloat162float(h[j]));
    }
    ((uint2*)hi)[i] = *(uint2*)h;
    ((uint2*)lo)[i] = *(uint2*)l;
}

// ---------------------------------------------------------------------------
// mma.sync GEMM:  C[M,N] = A[M,K] * B[N,K]^T (+ bias[N])
// bf16 hi/lo 3-term, fp32 accum. CTA 128x64, BK=64, 8 warps (2x4, warp 64x16).
// Separate hi/lo planes, 128B swizzled rows. 2-stage cp.async double buffer.
// Grid is BN=64-wide: kills wave-quantization tail (10.4 / 3.46 waves).
// ---------------------------------------------------------------------------
#define G_AH 0
#define G_AL 16384
#define G_BH 32768
#define G_BL 40960
#define G_STAGE 49152
#define GM_SMEM (2 * G_STAGE)       // 98304 per CTA (2 CTAs/SM = 192 KB)

template <bool BIAS, bool SPLIT>
__global__ void __launch_bounds__(256, 2) gemm_mma_kernel(
    const __nv_bfloat16* __restrict__ Ah, const __nv_bfloat16* __restrict__ Al,
    const __nv_bfloat16* __restrict__ Bh, const __nv_bfloat16* __restrict__ Bl,
    const float* __restrict__ bias, float* __restrict__ C,
    __nv_bfloat16* __restrict__ Ch, __nv_bfloat16* __restrict__ Cl,
    int M, int N, int K)
{
    extern __shared__ char sm[];
    const uint32_t smb = smem_u32(sm);
    const int tid  = threadIdx.x;
    const int wid  = tid >> 5;
    const int lane = tid & 31;
    const int m0 = blockIdx.y * 128;
    const int n0 = blockIdx.x * 64;
    const int wm = (wid >> 2) * 64;      // 2 m-groups of warps
    const int wn = (wid & 3) * 16;       // 4 n-groups

    const char* Ahc = (const char*)Ah;
    const char* Alc = (const char*)Al;
    const char* Bhc = (const char*)Bh;
    const char* Blc = (const char*)Bl;

    auto load_chunk = [&](int k0, int buf) {
        const uint32_t sb = smb + buf * G_STAGE;
        // A: 2 planes x 128 rows x 128B
        #pragma unroll
        for (int i = 0; i < 8; i++) {
            int idx = tid + i * 256;             // 0..2047
            int pl = idx >> 10;                  // 0=hi 1=lo
            int r  = (idx >> 3) & 127;
            int c  = (idx & 7) * 16;
            size_t gA = ((size_t)(m0 + r) * K + k0) * 2 + c;
            const char* src = (pl ? Alc : Ahc) + gA;
            CP_ASYNC16(sb + G_AH + pl * 16384 + SW128(r * 128 + c), src);
        }
        // B: 2 planes x 64 rows x 128B
        #pragma unroll
        for (int i = 0; i < 4; i++) {
            int idx = tid + i * 256;             // 0..1023
            int pl = idx >> 9;
            int r  = (idx >> 3) & 63;
            int c  = (idx & 7) * 16;
            size_t gB = ((size_t)(n0 + r) * K + k0) * 2 + c;
            const char* src = (pl ? Blc : Bhc) + gB;
            CP_ASYNC16(sb + G_BH + pl * 8192 + SW128(r * 128 + c), src);
        }
    };

    float acc[4][2][4];
    #pragma unroll
    for (int i = 0; i < 4; i++)
        #pragma unroll
        for (int j = 0; j < 2; j++)
            #pragma unroll
            for (int c = 0; c < 4; c++) acc[i][j][c] = 0.f;

    const int nch = K >> 6;                      // K/64
    load_chunk(0, 0); CP_COMMIT();

    const int a_row  = lane & 15;
    const int a_kofb = (lane >> 4) * 16;
    const int bq     = lane >> 3;
    const int b_row  = (bq >> 1) * 8 + (lane & 7);
    const int b_kofb = (bq & 1) * 16;

    for (int ch = 0; ch < nch; ch++) {
        if (ch + 1 < nch) { load_chunk((ch + 1) << 6, (ch + 1) & 1); CP_COMMIT(); CP_WAIT(1); }
        else              { CP_WAIT(0); }
        __syncthreads();
        const uint32_t sb = smb + (ch & 1) * G_STAGE;

        #pragma unroll
        for (int ks = 0; ks < 4; ks++) {
            const int kb = ks * 32;              // byte col of k16 step
            uint32_t bh[2][2], bl[2][2];
            {
                uint32_t row = (wn + b_row) * 128;
                LDMATRIX_X4(bh[0][0], bh[0][1], bh[1][0], bh[1][1],
                            sb + G_BH + SW128(row + kb + b_kofb));
                LDMATRIX_X4(bl[0][0], bl[0][1], bl[1][0], bl[1][1],
                            sb + G_BL + SW128(row + kb + b_kofb));
            }
            uint32_t ah[4][4], al[4][4];
            #pragma unroll
            for (int mi = 0; mi < 4; mi++) {
                uint32_t row = (wm + mi * 16 + a_row) * 128;
                LDMATRIX_X4(ah[mi][0], ah[mi][1], ah[mi][2], ah[mi][3],
                            sb + G_AH + SW128(row + kb + a_kofb));
                LDMATRIX_X4(al[mi][0], al[mi][1], al[mi][2], al[mi][3],
                            sb + G_AL + SW128(row + kb + a_kofb));
            }
            // term-major: 8 independent MMAs between accumulator reuse
            #pragma unroll
            for (int mi = 0; mi < 4; mi++)
                #pragma unroll
                for (int nj = 0; nj < 2; nj++)
                    MMA_BF16(acc[mi][nj][0], acc[mi][nj][1], acc[mi][nj][2], acc[mi][nj][3],
                             ah[mi][0], ah[mi][1], ah[mi][2], ah[mi][3],
                             bh[nj][0], bh[nj][1]);
            #pragma unroll
            for (int mi = 0; mi < 4; mi++)
                #pragma unroll
                for (int nj = 0; nj < 2; nj++)
                    MMA_BF16(acc[mi][nj][0], acc[mi][nj][1], acc[mi][nj][2], acc[mi][nj][3],
                             ah[mi][0], ah[mi][1], ah[mi][2], ah[mi][3],
                             bl[nj][0], bl[nj][1]);
            #pragma unroll
            for (int mi = 0; mi < 4; mi++)
                #pragma unroll
                for (int nj = 0; nj < 2; nj++)
                    MMA_BF16(acc[mi][nj][0], acc[mi][nj][1], acc[mi][nj][2], acc[mi][nj][3],
                             al[mi][0], al[mi][1], al[mi][2], al[mi][3],
                             bh[nj][0], bh[nj][1]);
        }
        __syncthreads();
    }

    const int g = lane >> 2, t = lane & 3;
    #pragma unroll
    for (int mi = 0; mi < 4; mi++) {
        const int row = m0 + wm + mi * 16 + g;
        #pragma unroll
        for (int nj = 0; nj < 2; nj++) {
            const int col = n0 + wn + nj * 8 + t * 2;
            if (SPLIT) {
                uint32_t lo0, lo1;
                uint32_t hi0 = pack_hi_lo(acc[mi][nj][0], acc[mi][nj][1], lo0);
                uint32_t hi1 = pack_hi_lo(acc[mi][nj][2], acc[mi][nj][3], lo1);
                *(uint32_t*)(Ch + (size_t)row * N + col)       = hi0;
                *(uint32_t*)(Cl + (size_t)row * N + col)       = lo0;
                *(uint32_t*)(Ch + (size_t)(row + 8) * N + col) = hi1;
                *(uint32_t*)(Cl + (size_t)(row + 8) * N + col) = lo1;
            } else {
                float b0 = 0.f, b1 = 0.f;
                if (BIAS) { b0 = bias[col]; b1 = bias[col + 1]; }
                float2 v0 = {acc[mi][nj][0] + b0, acc[mi][nj][1] + b1};
                float2 v1 = {acc[mi][nj][2] + b0, acc[mi][nj][3] + b1};
                *(float2*)(C + (size_t)row * N + col)       = v0;
                *(float2*)(C + (size_t)(row + 8) * N + col) = v1;
            }
        }
    }
}

// ---------------------------------------------------------------------------
// Flash attention with mma.sync (bf16 hi/lo 3-term, fp32 softmax/accum)
// grid (SEQ/128, HEADS, BATCH), 256 threads. SW128-swizzled smem, 2 CTAs/SM.
// (unchanged from R5/R7 passing version)
// ---------------------------------------------------------------------------
#define FA_OFF_QH 0
#define FA_OFF_QL 16384
#define FA_OFF_KV 32768
#define FA_KH 0
#define FA_KL 8192
#define FA_VH 16384
#define FA_VL 24576
#define FA_STAGE 32768
#define FA_OFF_MADD (FA_OFF_KV + 2 * FA_STAGE)   // 98304
#define FA_SMEM (FA_OFF_MADD + 2 * 64 * 4)       // 98816
#define FA_C1 0.18033688011112042f               // 0.125 * log2(e)

__global__ void __launch_bounds__(256, 2) flash_mma_kernel(
    const __nv_bfloat16* __restrict__ qkh, const __nv_bfloat16* __restrict__ qkl,
    const int* __restrict__ mask,
    __nv_bfloat16* __restrict__ oh, __nv_bfloat16* __restrict__ ol)
{
    extern __shared__ char sm[];
    const uint32_t smb = smem_u32(sm);
    const int tid = threadIdx.x, wid = tid >> 5, lane = tid & 31;
    const int qb = blockIdx.x, h = blockIdx.y, b = blockIdx.z;
    const int tok0 = b * SEQ + qb * 128;

    const char* qkhc = (const char*)qkh;
    const char* qklc = (const char*)qkl;

    auto load_kv = [&](int ch) {
        const uint32_t stg = smb + FA_OFF_KV + (ch & 1) * FA_STAGE;
        const int k0 = ch * 64;
        #pragma unroll
        for (int i = 0; i < 8; i++) {
            int idx = tid + i * 256;                 // 0..2047
            int tile = idx >> 9;                     // 0..3: KH,KL,VH,VL
            int r = (idx >> 3) & 63;
            int c = (idx & 7) * 16;
            size_t gK = ((size_t)(b * SEQ + k0 + r) * QKVF + EMB + h * HDIM) * 2 + c;
            size_t gV = gK + (size_t)EMB * 2;
            const char* src;
            if      (tile == 0) src = qkhc + gK;
            else if (tile == 1) src = qklc + gK;
            else if (tile == 2) src = qkhc + gV;
            else                src = qklc + gV;
            CP_ASYNC16(stg + tile * 8192 + SW128(r * 128 + c), src);
        }
        if (tid < 64) {
            float* md = (float*)(sm + FA_OFF_MADD) + (ch & 1) * 64;
            md[tid] = mask[b * SEQ + k0 + tid] ? 0.f : -1e9f;
        }
    };

    #pragma unroll
    for (int i = 0; i < 8; i++) {
        int idx = tid + i * 256;                     // 0..2047
        int t2 = idx >> 10;                          // 0 = hi, 1 = lo
        int r  = (idx >> 3) & 127;
        int c  = (idx & 7) * 16;
        size_t gb = ((size_t)(tok0 + r) * QKVF + h * HDIM) * 2 + c;
        const char* src = (t2 ? qklc : qkhc) + gb;
        CP_ASYNC16(smb + (t2 ? FA_OFF_QL : FA_OFF_QH) + SW128(r * 128 + c), src);
    }
    load_kv(0);
    CP_COMMIT();

    const int g  = lane >> 2, tq = lane & 3;
    const int a_row = lane & 15, a_kb = (lane >> 4) * 16;
    const int bq = lane >> 3;
    const int b_r = (bq >> 1) * 8 + (lane & 7), b_kb = (bq & 1) * 16;
    const int v_r = (bq & 1) * 8 + (lane & 7),  v_nb = (bq >> 1) * 16;

    float m0r = -1e30f, m1r = -1e30f, l0 = 0.f, l1 = 0.f;
    float o[8][4];
    #pragma unroll
    for (int j = 0; j < 8; j++)
        #pragma unroll
        for (int c = 0; c < 4; c++) o[j][c] = 0.f;

    const int NCH = SEQ / 64;
    for (int ch = 0; ch < NCH; ch++) {
        if (ch + 1 < NCH) { load_kv(ch + 1); CP_COMMIT(); CP_WAIT(1); }
        else              { CP_WAIT(0); }
        __syncthreads();
        const uint32_t stg = smb + FA_OFF_KV + (ch & 1) * FA_STAGE;

        float s[8][4];
        #pragma unroll
        for (int j = 0; j < 8; j++)
            #pragma unroll
            for (int c = 0; c < 4; c++) s[j][c] = 0.f;

        #pragma unroll
        for (int ks = 0; ks < 4; ks++) {
            const int kb = ks * 32;
            uint32_t qh[4], ql[4];
            uint32_t qrow = (wid * 16 + a_row) * 128;
            LDMATRIX_X4(qh[0], qh[1], qh[2], qh[3],
                        smb + FA_OFF_QH + SW128(qrow + kb + a_kb));
            LDMATRIX_X4(ql[0], ql[1], ql[2], ql[3],
                        smb + FA_OFF_QL + SW128(qrow + kb + a_kb));
            uint32_t kh[8][2], kl[8][2];
            #pragma unroll
            for (int p = 0; p < 4; p++) {
                uint32_t krow = (p * 16 + b_r) * 128;
                LDMATRIX_X4(kh[2*p][0], kh[2*p][1], kh[2*p+1][0], kh[2*p+1][1],
                            stg + FA_KH + SW128(krow + kb + b_kb));
                LDMATRIX_X4(kl[2*p][0], kl[2*p][1], kl[2*p+1][0], kl[2*p+1][1],
                            stg + FA_KL + SW128(krow + kb + b_kb));
            }
            #pragma unroll
            for (int j = 0; j < 8; j++)
                MMA_BF16(s[j][0], s[j][1], s[j][2], s[j][3],
                         qh[0], qh[1], qh[2], qh[3], kh[j][0], kh[j][1]);
            #pragma unroll
            for (int j = 0; j < 8; j++)
                MMA_BF16(s[j][0], s[j][1], s[j][2], s[j][3],
                         qh[0], qh[1], qh[2], qh[3], kl[j][0], kl[j][1]);
            #pragma unroll
            for (int j = 0; j < 8; j++)
                MMA_BF16(s[j][0], s[j][1], s[j][2], s[j][3],
                         ql[0], ql[1], ql[2], ql[3], kh[j][0], kh[j][1]);
        }

        const float* md = (const float*)(sm + FA_OFF_MADD) + (ch & 1) * 64;
        #pragma unroll
        for (int j = 0; j < 8; j++) {
            float m0 = md[j * 8 + tq * 2];
            float m1 = md[j * 8 + tq * 2 + 1];
            s[j][0] = fmaf(s[j][0], FA_C1, m0);
            s[j][1] = fmaf(s[j][1], FA_C1, m1);
            s[j][2] = fmaf(s[j][2], FA_C1, m0);
            s[j][3] = fmaf(s[j][3], FA_C1, m1);
        }
        float rm0 = -1e30f, rm1 = -1e30f;
        #pragma unroll
        for (int j = 0; j < 8; j++) {
            rm0 = fmaxf(rm0, fmaxf(s[j][0], s[j][1]));
            rm1 = fmaxf(rm1, fmaxf(s[j][2], s[j][3]));
        }
        rm0 = fmaxf(rm0, __shfl_xor_sync(0xffffffffu, rm0, 1));
        rm0 = fmaxf(rm0, __shfl_xor_sync(0xffffffffu, rm0, 2));
        rm1 = fmaxf(rm1, __shfl_xor_sync(0xffffffffu, rm1, 1));
        rm1 = fmaxf(rm1, __shfl_xor_sync(0xffffffffu, rm1, 2));
        const float mn0 = fmaxf(m0r, rm0);
        const float mn1 = fmaxf(m1r, rm1);
        const float al0 = ex2f(m0r - mn0);
        const float al1 = ex2f(m1r - mn1);
        m0r = mn0; m1r = mn1;

        float rs0 = 0.f, rs1 = 0.f;
        #pragma unroll
        for (int j = 0; j < 8; j++) {
            s[j][0] = ex2f(s[j][0] - mn0);
            s[j][1] = ex2f(s[j][1] - mn0);
            s[j][2] = ex2f(s[j][2] - mn1);
            s[j][3] = ex2f(s[j][3] - mn1);
            rs0 += s[j][0] + s[j][1];
            rs1 += s[j][2] + s[j][3];
        }
        rs0 += __shfl_xor_sync(0xffffffffu, rs0, 1);
        rs0 += __shfl_xor_sync(0xffffffffu, rs0, 2);
        rs1 += __shfl_xor_sync(0xffffffffu, rs1, 1);
        rs1 += __shfl_xor_sync(0xffffffffu, rs1, 2);
        l0 = l0 * al0 + rs0;
        l1 = l1 * al1 + rs1;

        #pragma unroll
        for (int j = 0; j < 8; j++) {
            o[j][0] *= al0; o[j][1] *= al0;
            o[j][2] *= al1; o[j][3] *= al1;
        }

        uint32_t pah[4][4], pal[4][4];
        #pragma unroll
        for (int ks = 0; ks < 4; ks++) {
            const int j0 = 2 * ks, j1 = 2 * ks + 1;
            pah[ks][0] = pack_hi_lo(s[j0][0], s[j0][1], pal[ks][0]);
            pah[ks][1] = pack_hi_lo(s[j0][2], s[j0][3], pal[ks][1]);
            pah[ks][2] = pack_hi_lo(s[j1][0], s[j1][1], pal[ks][2]);
            pah[ks][3] = pack_hi_lo(s[j1][2], s[j1][3], pal[ks][3]);
        }

        #pragma unroll
        for (int ks = 0; ks < 4; ks++) {
            uint32_t vh[4][4], vl[4][4];
            #pragma unroll
            for (int d = 0; d < 4; d++) {
                uint32_t voff = SW128((ks * 16 + v_r) * 128 + d * 32 + v_nb);
                LDMATRIX_X4_T(vh[d][0], vh[d][1], vh[d][2], vh[d][3], stg + FA_VH + voff);
                LDMATRIX_X4_T(vl[d][0], vl[d][1], vl[d][2], vl[d][3], stg + FA_VL + voff);
            }
            #pragma unroll
            for (int d = 0; d < 4; d++) {
                MMA_BF16(o[2*d][0], o[2*d][1], o[2*d][2], o[2*d][3],
                         pah[ks][0], pah[ks][1], pah[ks][2], pah[ks][3], vh[d][0], vh[d][1]);
                MMA_BF16(o[2*d+1][0], o[2*d+1][1], o[2*d+1][2], o[2*d+1][3],
                         pah[ks][0], pah[ks][1], pah[ks][2], pah[ks][3], vh[d][2], vh[d][3]);
            }
            #pragma unroll
            for (int d = 0; d < 4; d++) {
                MMA_BF16(o[2*d][0], o[2*d][1], o[2*d][2], o[2*d][3],
                         pah[ks][0], pah[ks][1], pah[ks][2], pah[ks][3], vl[d][0], vl[d][1]);
                MMA_BF16(o[2*d+1][0], o[2*d+1][1], o[2*d+1][2], o[2*d+1][3],
                         pah[ks][0], pah[ks][1], pah[ks][2], pah[ks][3], vl[d][2], vl[d][3]);
            }
            #pragma unroll
            for (int d = 0; d < 4; d++) {
                MMA_BF16(o[2*d][0], o[2*d][1], o[2*d][2], o[2*d][3],
                         pal[ks][0], pal[ks][1], pal[ks][2], pal[ks][3], vh[d][0], vh[d][1]);
                MMA_BF16(o[2*d+1][0], o[2*d+1][1], o[2*d+1][2], o[2*d+1][3],
                         pal[ks][0], pal[ks][1], pal[ks][2], pal[ks][3], vh[d][2], vh[d][3]);
            }
        }
        __syncthreads();
    }

    const float inv0 = 1.f / l0;
    const float inv1 = 1.f / l1;
    const int r0 = tok0 + wid * 16 + g;
    const int r1 = r0 + 8;
    #pragma unroll
    for (int j = 0; j < 8; j++) {
        const int col = h * HDIM + j * 8 + tq * 2;
        uint32_t lo0, lo1;
        uint32_t hi0 = pack_hi_lo(o[j][0] * inv0, o[j][1] * inv0, lo0);
        uint32_t hi1 = pack_hi_lo(o[j][2] * inv1, o[j][3] * inv1, lo1);
        *(uint32_t*)(oh + (size_t)r0 * EMB + col) = hi0;
        *(uint32_t*)(ol + (size_t)r0 * EMB + col) = lo0;
        *(uint32_t*)(oh + (size_t)r1 * EMB + col) = hi1;
        *(uint32_t*)(ol + (size_t)r1 * EMB + col) = lo1;
    }
}

// ---------------------------------------------------------------------------
extern "C" void kernel_launch(void* const* d_in, const int* in_sizes, int n_in,
                              void* d_out, int out_size)
{
    const float* x     = (const float*)d_in[0];
    const float* w_qkv = (const float*)d_in[1];
    const float* w_out = (const float*)d_in[2];
    const float* b_out = (const float*)d_in[3];
    const int*   mask  = (const int*)  d_in[4];
    float* out = (float*)d_out;

    __nv_bfloat16 *xh, *xl, *wqh, *wql, *woh, *wol, *qkh, *qkl, *ath, *atl;
    cudaGetSymbolAddress((void**)&xh,  g_xh);
    cudaGetSymbolAddress((void**)&xl,  g_xl);
    cudaGetSymbolAddress((void**)&wqh, g_wqkvh);
    cudaGetSymbolAddress((void**)&wql, g_wqkvl);
    cudaGetSymbolAddress((void**)&woh, g_wouth);
    cudaGetSymbolAddress((void**)&wol, g_woutl);
    cudaGetSymbolAddress((void**)&qkh, g_qkvh);
    cudaGetSymbolAddress((void**)&qkl, g_qkvl);
    cudaGetSymbolAddress((void**)&ath, g_atth);
    cudaGetSymbolAddress((void**)&atl, g_attl);

    cudaFuncSetAttribute((const void*)gemm_mma_kernel<false, true>,
                         cudaFuncAttributeMaxDynamicSharedMemorySize, GM_SMEM);
    cudaFuncSetAttribute((const void*)gemm_mma_kernel<true, false>,
                         cudaFuncAttributeMaxDynamicSharedMemorySize, GM_SMEM);
    cudaFuncSetAttribute((const void*)flash_mma_kernel,
                         cudaFuncAttributeMaxDynamicSharedMemorySize, FA_SMEM);

    // 0) splits
    {
        int n4 = TOK * EMB / 4;
        split_kernel<<<(n4 + 255) / 256, 256>>>((const float4*)x, xh, xl, n4);
        n4 = QKVF * EMB / 4;
        split_kernel<<<(n4 + 255) / 256, 256>>>((const float4*)w_qkv, wqh, wql, n4);
        n4 = EMB * EMB / 4;
        split_kernel<<<(n4 + 255) / 256, 256>>>((const float4*)w_out, woh, wol, n4);
    }

    // 1) QKV projection -> bf16 hi/lo qkv   (grid 48x64 = 3072 CTAs)
    {
        dim3 grid(QKVF / 64, TOK / 128);
        gemm_mma_kernel<false, true><<<grid, 256, GM_SMEM>>>(
            xh, xl, wqh, wql, nullptr, nullptr, qkh, qkl, TOK, QKVF, EMB);
    }

    // 2) Flash attention -> bf16 hi/lo attn
    {
        dim3 grid(SEQ / 128, HEADS, BATCH);
        flash_mma_kernel<<<grid, 256, FA_SMEM>>>(qkh, qkl, mask, ath, atl);
    }

    // 3) Output projection + bias -> f32 out   (grid 16x64 = 1024 CTAs)
    {
        dim3 grid(EMB / 64, TOK / 128);
        gemm_mma_kernel<true, false><<<grid, 256, GM_SMEM>>>(
            ath, atl, woh, wol, b_out, out, nullptr, nullptr, TOK, EMB, EMB);
    }
}

// round 9
// speedup vs baseline: 1.2382x; 1.0105x over previous
#include <cuda_runtime.h>
#include <cuda_bf16.h>
#include <math.h>
#include <stdint.h>

// Problem constants
#define BATCH 4
#define SEQ   2048
#define EMB   1024
#define HEADS 16
#define HDIM  64
#define TOK   (BATCH * SEQ)          // 8192
#define QKVF  (3 * EMB)              // 3072

// Scratch (device globals — no allocation allowed)
__device__ __nv_bfloat16 g_xh[(size_t)TOK * EMB];
__device__ __nv_bfloat16 g_xl[(size_t)TOK * EMB];
__device__ __nv_bfloat16 g_wqkvh[(size_t)QKVF * EMB];
__device__ __nv_bfloat16 g_wqkvl[(size_t)QKVF * EMB];
__device__ __nv_bfloat16 g_wouth[(size_t)EMB * EMB];
__device__ __nv_bfloat16 g_woutl[(size_t)EMB * EMB];
__device__ __nv_bfloat16 g_qkvh[(size_t)TOK * QKVF];
__device__ __nv_bfloat16 g_qkvl[(size_t)TOK * QKVF];
__device__ __nv_bfloat16 g_atth[(size_t)TOK * EMB];
__device__ __nv_bfloat16 g_attl[(size_t)TOK * EMB];

// ---------------------------------------------------------------------------
// PTX helpers — only sm_80+ features (compute_103 baseline safe)
// ---------------------------------------------------------------------------
__device__ __forceinline__ uint32_t smem_u32(const void* p) {
    uint32_t a;
    asm("{ .reg .u64 t; cvta.to.shared.u64 t, %1; cvt.u32.u64 %0, t; }"
        : "=r"(a) : "l"(p));
    return a;
}

#define CP_ASYNC16(dst, src) \
    asm volatile("cp.async.cg.shared.global [%0], [%1], 16;" :: "r"(dst), "l"(src))
#define CP_COMMIT() asm volatile("cp.async.commit_group;")
#define CP_WAIT(n)  asm volatile("cp.async.wait_group %0;" :: "n"(n))

#define LDMATRIX_X4(r0, r1, r2, r3, addr) \
    asm volatile("ldmatrix.sync.aligned.m8n8.x4.shared.b16 {%0,%1,%2,%3}, [%4];" \
                 : "=r"(r0), "=r"(r1), "=r"(r2), "=r"(r3) : "r"(addr))
#define LDMATRIX_X4_T(r0, r1, r2, r3, addr) \
    asm volatile("ldmatrix.sync.aligned.m8n8.x4.trans.shared.b16 {%0,%1,%2,%3}, [%4];" \
                 : "=r"(r0), "=r"(r1), "=r"(r2), "=r"(r3) : "r"(addr))

#define MMA_BF16(c0, c1, c2, c3, a0, a1, a2, a3, b0, b1) \
    asm volatile("mma.sync.aligned.m16n8k16.row.col.f32.bf16.bf16.f32 " \
                 "{%0,%1,%2,%3}, {%4,%5,%6,%7}, {%8,%9}, {%0,%1,%2,%3};" \
                 : "+f"(c0), "+f"(c1), "+f"(c2), "+f"(c3) \
                 : "r"(a0), "r"(a1), "r"(a2), "r"(a3), "r"(b0), "r"(b1))

__device__ __forceinline__ float ex2f(float x) {
    float y;
    asm("ex2.approx.f32 %0, %1;" : "=f"(y) : "f"(x));
    return y;
}

__device__ __forceinline__ uint32_t pack_hi_lo(float a, float b, uint32_t& lo) {
    __nv_bfloat162 h = __floats2bfloat162_rn(a, b);
    float ra = a - __bfloat162float(h.x);
    float rb = b - __bfloat162float(h.y);
    __nv_bfloat162 r = __floats2bfloat162_rn(ra, rb);
    lo = reinterpret_cast<uint32_t&>(r);
    return reinterpret_cast<uint32_t&>(h);
}

// SW128 XOR swizzle on byte offsets (rows of 128B): conflict-free ldmatrix
#define SW128(off) ((uint32_t)(off) ^ ((((uint32_t)(off)) >> 3) & 0x70))

// ---------------------------------------------------------------------------
// fp32 -> bf16 hi/lo split
// ---------------------------------------------------------------------------
__global__ void __launch_bounds__(256) split_kernel(
    const float4* __restrict__ in, __nv_bfloat16* __restrict__ hi,
    __nv_bfloat16* __restrict__ lo, int n4)
{
    int i = blockIdx.x * blockDim.x + threadIdx.x;
    if (i >= n4) return;
    float4 v = in[i];
    float f[4] = {v.x, v.y, v.z, v.w};
    __nv_bfloat16 h[4], l[4];
    #pragma unroll
    for (int j = 0; j < 4; j++) {
        h[j] = __float2bfloat16(f[j]);
        l[j] = __float2bfloat16(f[j] - __bfloat162float(h[j]));
    }
    ((uint2*)hi)[i] = *(uint2*)h;
    ((uint2*)lo)[i] = *(uint2*)l;
}

// ---------------------------------------------------------------------------
// mma.sync GEMM:  C[M,N] = A[M,K] * B[N,K]^T (+ bias[N])
// bf16 hi/lo 3-term, fp32 accum. CTA 128x64, BK=64, 8 warps 4x2 (warp 32x32).
// 8 LDSM.x4 per 24 MMAs per k16-step (was 10 with 64x16 warps).
// ---------------------------------------------------------------------------
#define G_AH 0
#define G_AL 16384
#define G_BH 32768
#define G_BL 40960
#define G_STAGE 49152
#define GM_SMEM (2 * G_STAGE)       // 98304 per CTA (2 CTAs/SM = 192 KB)

template <bool BIAS, bool SPLIT>
__global__ void __launch_bounds__(256, 2) gemm_mma_kernel(
    const __nv_bfloat16* __restrict__ Ah, const __nv_bfloat16* __restrict__ Al,
    const __nv_bfloat16* __restrict__ Bh, const __nv_bfloat16* __restrict__ Bl,
    const float* __restrict__ bias, float* __restrict__ C,
    __nv_bfloat16* __restrict__ Ch, __nv_bfloat16* __restrict__ Cl,
    int M, int N, int K)
{
    extern __shared__ char sm[];
    const uint32_t smb = smem_u32(sm);
    const int tid  = threadIdx.x;
    const int wid  = tid >> 5;
    const int lane = tid & 31;
    const int m0 = blockIdx.y * 128;
    const int n0 = blockIdx.x * 64;
    const int wm = (wid >> 1) * 32;      // 4 m-groups of 32 rows
    const int wn = (wid & 1) * 32;       // 2 n-groups of 32 cols

    const char* Ahc = (const char*)Ah;
    const char* Alc = (const char*)Al;
    const char* Bhc = (const char*)Bh;
    const char* Blc = (const char*)Bl;

    auto load_chunk = [&](int k0, int buf) {
        const uint32_t sb = smb + buf * G_STAGE;
        // A: 2 planes x 128 rows x 128B
        #pragma unroll
        for (int i = 0; i < 8; i++) {
            int idx = tid + i * 256;             // 0..2047
            int pl = idx >> 10;                  // 0=hi 1=lo
            int r  = (idx >> 3) & 127;
            int c  = (idx & 7) * 16;
            size_t gA = ((size_t)(m0 + r) * K + k0) * 2 + c;
            const char* src = (pl ? Alc : Ahc) + gA;
            CP_ASYNC16(sb + G_AH + pl * 16384 + SW128(r * 128 + c), src);
        }
        // B: 2 planes x 64 rows x 128B
        #pragma unroll
        for (int i = 0; i < 4; i++) {
            int idx = tid + i * 256;             // 0..1023
            int pl = idx >> 9;
            int r  = (idx >> 3) & 63;
            int c  = (idx & 7) * 16;
            size_t gB = ((size_t)(n0 + r) * K + k0) * 2 + c;
            const char* src = (pl ? Blc : Bhc) + gB;
            CP_ASYNC16(sb + G_BH + pl * 8192 + SW128(r * 128 + c), src);
        }
    };

    float acc[2][4][4];
    #pragma unroll
    for (int i = 0; i < 2; i++)
        #pragma unroll
        for (int j = 0; j < 4; j++)
            #pragma unroll
            for (int c = 0; c < 4; c++) acc[i][j][c] = 0.f;

    const int nch = K >> 6;                      // K/64
    load_chunk(0, 0); CP_COMMIT();

    const int a_row  = lane & 15;
    const int a_kofb = (lane >> 4) * 16;
    const int bq     = lane >> 3;
    const int b_row  = (bq >> 1) * 8 + (lane & 7);
    const int b_kofb = (bq & 1) * 16;

    for (int ch = 0; ch < nch; ch++) {
        if (ch + 1 < nch) { load_chunk((ch + 1) << 6, (ch + 1) & 1); CP_COMMIT(); CP_WAIT(1); }
        else              { CP_WAIT(0); }
        __syncthreads();
        const uint32_t sb = smb + (ch & 1) * G_STAGE;

        #pragma unroll
        for (int ks = 0; ks < 4; ks++) {
            const int kb = ks * 32;              // byte col of k16 step
            // B fragments: 4 nj (8-wide each) from 2 x4 loads, hi & lo planes
            uint32_t bh[4][2], bl[4][2];
            #pragma unroll
            for (int p = 0; p < 2; p++) {
                uint32_t row = (wn + p * 16 + b_row) * 128;
                LDMATRIX_X4(bh[2*p][0], bh[2*p][1], bh[2*p+1][0], bh[2*p+1][1],
                            sb + G_BH + SW128(row + kb + b_kofb));
                LDMATRIX_X4(bl[2*p][0], bl[2*p][1], bl[2*p+1][0], bl[2*p+1][1],
                            sb + G_BL + SW128(row + kb + b_kofb));
            }
            // A fragments: 2 mi x (hi, lo)
            uint32_t ah[2][4], al[2][4];
            #pragma unroll
            for (int mi = 0; mi < 2; mi++) {
                uint32_t row = (wm + mi * 16 + a_row) * 128;
                LDMATRIX_X4(ah[mi][0], ah[mi][1], ah[mi][2], ah[mi][3],
                            sb + G_AH + SW128(row + kb + a_kofb));
                LDMATRIX_X4(al[mi][0], al[mi][1], al[mi][2], al[mi][3],
                            sb + G_AL + SW128(row + kb + a_kofb));
            }
            // term-major: 8 independent MMAs between accumulator reuse
            #pragma unroll
            for (int mi = 0; mi < 2; mi++)
                #pragma unroll
                for (int nj = 0; nj < 4; nj++)
                    MMA_BF16(acc[mi][nj][0], acc[mi][nj][1], acc[mi][nj][2], acc[mi][nj][3],
                             ah[mi][0], ah[mi][1], ah[mi][2], ah[mi][3],
                             bh[nj][0], bh[nj][1]);
            #pragma unroll
            for (int mi = 0; mi < 2; mi++)
                #pragma unroll
                for (int nj = 0; nj < 4; nj++)
                    MMA_BF16(acc[mi][nj][0], acc[mi][nj][1], acc[mi][nj][2], acc[mi][nj][3],
                             ah[mi][0], ah[mi][1], ah[mi][2], ah[mi][3],
                             bl[nj][0], bl[nj][1]);
            #pragma unroll
            for (int mi = 0; mi < 2; mi++)
                #pragma unroll
                for (int nj = 0; nj < 4; nj++)
                    MMA_BF16(acc[mi][nj][0], acc[mi][nj][1], acc[mi][nj][2], acc[mi][nj][3],
                             al[mi][0], al[mi][1], al[mi][2], al[mi][3],
                             bh[nj][0], bh[nj][1]);
        }
        __syncthreads();
    }

    const int g = lane >> 2, t = lane & 3;
    #pragma unroll
    for (int mi = 0; mi < 2; mi++) {
        const int row = m0 + wm + mi * 16 + g;
        #pragma unroll
        for (int nj = 0; nj < 4; nj++) {
            const int col = n0 + wn + nj * 8 + t * 2;
            if (SPLIT) {
                uint32_t lo0, lo1;
                uint32_t hi0 = pack_hi_lo(acc[mi][nj][0], acc[mi][nj][1], lo0);
                uint32_t hi1 = pack_hi_lo(acc[mi][nj][2], acc[mi][nj][3], lo1);
                *(uint32_t*)(Ch + (size_t)row * N + col)       = hi0;
                *(uint32_t*)(Cl + (size_t)row * N + col)       = lo0;
                *(uint32_t*)(Ch + (size_t)(row + 8) * N + col) = hi1;
                *(uint32_t*)(Cl + (size_t)(row + 8) * N + col) = lo1;
            } else {
                float b0 = 0.f, b1 = 0.f;
                if (BIAS) { b0 = bias[col]; b1 = bias[col + 1]; }
                float2 v0 = {acc[mi][nj][0] + b0, acc[mi][nj][1] + b1};
                float2 v1 = {acc[mi][nj][2] + b0, acc[mi][nj][3] + b1};
                *(float2*)(C + (size_t)row * N + col)       = v0;
                *(float2*)(C + (size_t)(row + 8) * N + col) = v1;
            }
        }
    }
}

// ---------------------------------------------------------------------------
// Flash attention with mma.sync (bf16 hi/lo 3-term, fp32 softmax/accum)
// grid (SEQ/128, HEADS, BATCH), 256 threads. SW128-swizzled smem, 2 CTAs/SM.
// (unchanged from R8 passing version)
// ---------------------------------------------------------------------------
#define FA_OFF_QH 0
#define FA_OFF_QL 16384
#define FA_OFF_KV 32768
#define FA_KH 0
#define FA_KL 8192
#define FA_VH 16384
#define FA_VL 24576
#define FA_STAGE 32768
#define FA_OFF_MADD (FA_OFF_KV + 2 * FA_STAGE)   // 98304
#define FA_SMEM (FA_OFF_MADD + 2 * 64 * 4)       // 98816
#define FA_C1 0.18033688011112042f               // 0.125 * log2(e)

__global__ void __launch_bounds__(256, 2) flash_mma_kernel(
    const __nv_bfloat16* __restrict__ qkh, const __nv_bfloat16* __restrict__ qkl,
    const int* __restrict__ mask,
    __nv_bfloat16* __restrict__ oh, __nv_bfloat16* __restrict__ ol)
{
    extern __shared__ char sm[];
    const uint32_t smb = smem_u32(sm);
    const int tid = threadIdx.x, wid = tid >> 5, lane = tid & 31;
    const int qb = blockIdx.x, h = blockIdx.y, b = blockIdx.z;
    const int tok0 = b * SEQ + qb * 128;

    const char* qkhc = (const char*)qkh;
    const char* qklc = (const char*)qkl;

    auto load_kv = [&](int ch) {
        const uint32_t stg = smb + FA_OFF_KV + (ch & 1) * FA_STAGE;
        const int k0 = ch * 64;
        #pragma unroll
        for (int i = 0; i < 8; i++) {
            int idx = tid + i * 256;                 // 0..2047
            int tile = idx >> 9;                     // 0..3: KH,KL,VH,VL
            int r = (idx >> 3) & 63;
            int c = (idx & 7) * 16;
            size_t gK = ((size_t)(b * SEQ + k0 + r) * QKVF + EMB + h * HDIM) * 2 + c;
            size_t gV = gK + (size_t)EMB * 2;
            const char* src;
            if      (tile == 0) src = qkhc + gK;
            else if (tile == 1) src = qklc + gK;
            else if (tile == 2) src = qkhc + gV;
            else                src = qklc + gV;
            CP_ASYNC16(stg + tile * 8192 + SW128(r * 128 + c), src);
        }
        if (tid < 64) {
            float* md = (float*)(sm + FA_OFF_MADD) + (ch & 1) * 64;
            md[tid] = mask[b * SEQ + k0 + tid] ? 0.f : -1e9f;
        }
    };

    #pragma unroll
    for (int i = 0; i < 8; i++) {
        int idx = tid + i * 256;                     // 0..2047
        int t2 = idx >> 10;                          // 0 = hi, 1 = lo
        int r  = (idx >> 3) & 127;
        int c  = (idx & 7) * 16;
        size_t gb = ((size_t)(tok0 + r) * QKVF + h * HDIM) * 2 + c;
        const char* src = (t2 ? qklc : qkhc) + gb;
        CP_ASYNC16(smb + (t2 ? FA_OFF_QL : FA_OFF_QH) + SW128(r * 128 + c), src);
    }
    load_kv(0);
    CP_COMMIT();

    const int g  = lane >> 2, tq = lane & 3;
    const int a_row = lane & 15, a_kb = (lane >> 4) * 16;
    const int bq = lane >> 3;
    const int b_r = (bq >> 1) * 8 + (lane & 7), b_kb = (bq & 1) * 16;
    const int v_r = (bq & 1) * 8 + (lane & 7),  v_nb = (bq >> 1) * 16;

    float m0r = -1e30f, m1r = -1e30f, l0 = 0.f, l1 = 0.f;
    float o[8][4];
    #pragma unroll
    for (int j = 0; j < 8; j++)
        #pragma unroll
        for (int c = 0; c < 4; c++) o[j][c] = 0.f;

    const int NCH = SEQ / 64;
    for (int ch = 0; ch < NCH; ch++) {
        if (ch + 1 < NCH) { load_kv(ch + 1); CP_COMMIT(); CP_WAIT(1); }
        else              { CP_WAIT(0); }
        __syncthreads();
        const uint32_t stg = smb + FA_OFF_KV + (ch & 1) * FA_STAGE;

        float s[8][4];
        #pragma unroll
        for (int j = 0; j < 8; j++)
            #pragma unroll
            for (int c = 0; c < 4; c++) s[j][c] = 0.f;

        #pragma unroll
        for (int ks = 0; ks < 4; ks++) {
            const int kb = ks * 32;
            uint32_t qh[4], ql[4];
            uint32_t qrow = (wid * 16 + a_row) * 128;
            LDMATRIX_X4(qh[0], qh[1], qh[2], qh[3],
                        smb + FA_OFF_QH + SW128(qrow + kb + a_kb));
            LDMATRIX_X4(ql[0], ql[1], ql[2], ql[3],
                        smb + FA_OFF_QL + SW128(qrow + kb + a_kb));
            uint32_t kh[8][2], kl[8][2];
            #pragma unroll
            for (int p = 0; p < 4; p++) {
                uint32_t krow = (p * 16 + b_r) * 128;
                LDMATRIX_X4(kh[2*p][0], kh[2*p][1], kh[2*p+1][0], kh[2*p+1][1],
                            stg + FA_KH + SW128(krow + kb + b_kb));
                LDMATRIX_X4(kl[2*p][0], kl[2*p][1], kl[2*p+1][0], kl[2*p+1][1],
                            stg + FA_KL + SW128(krow + kb + b_kb));
            }
            #pragma unroll
            for (int j = 0; j < 8; j++)
                MMA_BF16(s[j][0], s[j][1], s[j][2], s[j][3],
                         qh[0], qh[1], qh[2], qh[3], kh[j][0], kh[j][1]);
            #pragma unroll
            for (int j = 0; j < 8; j++)
                MMA_BF16(s[j][0], s[j][1], s[j][2], s[j][3],
                         qh[0], qh[1], qh[2], qh[3], kl[j][0], kl[j][1]);
            #pragma unroll
            for (int j = 0; j < 8; j++)
                MMA_BF16(s[j][0], s[j][1], s[j][2], s[j][3],
                         ql[0], ql[1], ql[2], ql[3], kh[j][0], kh[j][1]);
        }

        const float* md = (const float*)(sm + FA_OFF_MADD) + (ch & 1) * 64;
        #pragma unroll
        for (int j = 0; j < 8; j++) {
            float m0 = md[j * 8 + tq * 2];
            float m1 = md[j * 8 + tq * 2 + 1];
            s[j][0] = fmaf(s[j][0], FA_C1, m0);
            s[j][1] = fmaf(s[j][1], FA_C1, m1);
            s[j][2] = fmaf(s[j][2], FA_C1, m0);
            s[j][3] = fmaf(s[j][3], FA_C1, m1);
        }
        float rm0 = -1e30f, rm1 = -1e30f;
        #pragma unroll
        for (int j = 0; j < 8; j++) {
            rm0 = fmaxf(rm0, fmaxf(s[j][0], s[j][1]));
            rm1 = fmaxf(rm1, fmaxf(s[j][2], s[j][3]));
        }
        rm0 = fmaxf(rm0, __shfl_xor_sync(0xffffffffu, rm0, 1));
        rm0 = fmaxf(rm0, __shfl_xor_sync(0xffffffffu, rm0, 2));
        rm1 = fmaxf(rm1, __shfl_xor_sync(0xffffffffu, rm1, 1));
        rm1 = fmaxf(rm1, __shfl_xor_sync(0xffffffffu, rm1, 2));
        const float mn0 = fmaxf(m0r, rm0);
        const float mn1 = fmaxf(m1r, rm1);
        const float al0 = ex2f(m0r - mn0);
        const float al1 = ex2f(m1r - mn1);
        m0r = mn0; m1r = mn1;

        float rs0 = 0.f, rs1 = 0.f;
        #pragma unroll
        for (int j = 0; j < 8; j++) {
            s[j][0] = ex2f(s[j][0] - mn0);
            s[j][1] = ex2f(s[j][1] - mn0);
            s[j][2] = ex2f(s[j][2] - mn1);
            s[j][3] = ex2f(s[j][3] - mn1);
            rs0 += s[j][0] + s[j][1];
            rs1 += s[j][2] + s[j][3];
        }
        rs0 += __shfl_xor_sync(0xffffffffu, rs0, 1);
        rs0 += __shfl_xor_sync(0xffffffffu, rs0, 2);
        rs1 += __shfl_xor_sync(0xffffffffu, rs1, 1);
        rs1 += __shfl_xor_sync(0xffffffffu, rs1, 2);
        l0 = l0 * al0 + rs0;
        l1 = l1 * al1 + rs1;

        #pragma unroll
        for (int j = 0; j < 8; j++) {
            o[j][0] *= al0; o[j][1] *= al0;
            o[j][2] *= al1; o[j][3] *= al1;
        }

        uint32_t pah[4][4], pal[4][4];
        #pragma unroll
        for (int ks = 0; ks < 4; ks++) {
            const int j0 = 2 * ks, j1 = 2 * ks + 1;
            pah[ks][0] = pack_hi_lo(s[j0][0], s[j0][1], pal[ks][0]);
            pah[ks][1] = pack_hi_lo(s[j0][2], s[j0][3], pal[ks][1]);
            pah[ks][2] = pack_hi_lo(s[j1][0], s[j1][1], pal[ks][2]);
            pah[ks][3] = pack_hi_lo(s[j1][2], s[j1][3], pal[ks][3]);
        }

        #pragma unroll
        for (int ks = 0; ks < 4; ks++) {
            uint32_t vh[4][4], vl[4][4];
            #pragma unroll
            for (int d = 0; d < 4; d++) {
                uint32_t voff = SW128((ks * 16 + v_r) * 128 + d * 32 + v_nb);
                LDMATRIX_X4_T(vh[d][0], vh[d][1], vh[d][2], vh[d][3], stg + FA_VH + voff);
                LDMATRIX_X4_T(vl[d][0], vl[d][1], vl[d][2], vl[d][3], stg + FA_VL + voff);
            }
            #pragma unroll
            for (int d = 0; d < 4; d++) {
                MMA_BF16(o[2*d][0], o[2*d][1], o[2*d][2], o[2*d][3],
                         pah[ks][0], pah[ks][1], pah[ks][2], pah[ks][3], vh[d][0], vh[d][1]);
                MMA_BF16(o[2*d+1][0], o[2*d+1][1], o[2*d+1][2], o[2*d+1][3],
                         pah[ks][0], pah[ks][1], pah[ks][2], pah[ks][3], vh[d][2], vh[d][3]);
            }
            #pragma unroll
            for (int d = 0; d < 4; d++) {
                MMA_BF16(o[2*d][0], o[2*d][1], o[2*d][2], o[2*d][3],
                         pah[ks][0], pah[ks][1], pah[ks][2], pah[ks][3], vl[d][0], vl[d][1]);
                MMA_BF16(o[2*d+1][0], o[2*d+1][1], o[2*d+1][2], o[2*d+1][3],
                         pah[ks][0], pah[ks][1], pah[ks][2], pah[ks][3], vl[d][2], vl[d][3]);
            }
            #pragma unroll
            for (int d = 0; d < 4; d++) {
                MMA_BF16(o[2*d][0], o[2*d][1], o[2*d][2], o[2*d][3],
                         pal[ks][0], pal[ks][1], pal[ks][2], pal[ks][3], vh[d][0], vh[d][1]);
                MMA_BF16(o[2*d+1][0], o[2*d+1][1], o[2*d+1][2], o[2*d+1][3],
                         pal[ks][0], pal[ks][1], pal[ks][2], pal[ks][3], vh[d][2], vh[d][3]);
            }
        }
        __syncthreads();
    }

    const float inv0 = 1.f / l0;
    const float inv1 = 1.f / l1;
    const int r0 = tok0 + wid * 16 + g;
    const int r1 = r0 + 8;
    #pragma unroll
    for (int j = 0; j < 8; j++) {
        const int col = h * HDIM + j * 8 + tq * 2;
        uint32_t lo0, lo1;
        uint32_t hi0 = pack_hi_lo(o[j][0] * inv0, o[j][1] * inv0, lo0);
        uint32_t hi1 = pack_hi_lo(o[j][2] * inv1, o[j][3] * inv1, lo1);
        *(uint32_t*)(oh + (size_t)r0 * EMB + col) = hi0;
        *(uint32_t*)(ol + (size_t)r0 * EMB + col) = lo0;
        *(uint32_t*)(oh + (size_t)r1 * EMB + col) = hi1;
        *(uint32_t*)(ol + (size_t)r1 * EMB + col) = lo1;
    }
}

// ---------------------------------------------------------------------------
extern "C" void kernel_launch(void* const* d_in, const int* in_sizes, int n_in,
                              void* d_out, int out_size)
{
    const float* x     = (const float*)d_in[0];
    const float* w_qkv = (const float*)d_in[1];
    const float* w_out = (const float*)d_in[2];
    const float* b_out = (const float*)d_in[3];
    const int*   mask  = (const int*)  d_in[4];
    float* out = (float*)d_out;

    __nv_bfloat16 *xh, *xl, *wqh, *wql, *woh, *wol, *qkh, *qkl, *ath, *atl;
    cudaGetSymbolAddress((void**)&xh,  g_xh);
    cudaGetSymbolAddress((void**)&xl,  g_xl);
    cudaGetSymbolAddress((void**)&wqh, g_wqkvh);
    cudaGetSymbolAddress((void**)&wql, g_wqkvl);
    cudaGetSymbolAddress((void**)&woh, g_wouth);
    cudaGetSymbolAddress((void**)&wol, g_woutl);
    cudaGetSymbolAddress((void**)&qkh, g_qkvh);
    cudaGetSymbolAddress((void**)&qkl, g_qkvl);
    cudaGetSymbolAddress((void**)&ath, g_atth);
    cudaGetSymbolAddress((void**)&atl, g_attl);

    cudaFuncSetAttribute((const void*)gemm_mma_kernel<false, true>,
                         cudaFuncAttributeMaxDynamicSharedMemorySize, GM_SMEM);
    cudaFuncSetAttribute((const void*)gemm_mma_kernel<true, false>,
                         cudaFuncAttributeMaxDynamicSharedMemorySize, GM_SMEM);
    cudaFuncSetAttribute((const void*)flash_mma_kernel,
                         cudaFuncAttributeMaxDynamicSharedMemorySize, FA_SMEM);

    // 0) splits
    {
        int n4 = TOK * EMB / 4;
        split_kernel<<<(n4 + 255) / 256, 256>>>((const float4*)x, xh, xl, n4);
        n4 = QKVF * EMB / 4;
        split_kernel<<<(n4 + 255) / 256, 256>>>((const float4*)w_qkv, wqh, wql, n4);
        n4 = EMB * EMB / 4;
        split_kernel<<<(n4 + 255) / 256, 256>>>((const float4*)w_out, woh, wol, n4);
    }

    // 1) QKV projection -> bf16 hi/lo qkv   (grid 48x64 = 3072 CTAs)
    {
        dim3 grid(QKVF / 64, TOK / 128);
        gemm_mma_kernel<false, true><<<grid, 256, GM_SMEM>>>(
            xh, xl, wqh, wql, nullptr, nullptr, qkh, qkl, TOK, QKVF, EMB);
    }

    // 2) Flash attention -> bf16 hi/lo attn
    {
        dim3 grid(SEQ / 128, HEADS, BATCH);
        flash_mma_kernel<<<grid, 256, FA_SMEM>>>(qkh, qkl, mask, ath, atl);
    }

    // 3) Output projection + bias -> f32 out   (grid 16x64 = 1024 CTAs)
    {
        dim3 grid(EMB / 64, TOK / 128);
        gemm_mma_kernel<true, false><<<grid, 256, GM_SMEM>>>(
            ath, atl, woh, wol, b_out, out, nullptr, nullptr, TOK, EMB, EMB);
    }
}